// round 1
// baseline (speedup 1.0000x reference)
#include <cuda_runtime.h>
#include <math.h>
#include <stdint.h>

#define BATCH 64
#define SEQT  512
#define EDIM  300
#define KPAD  304
#define HC    512
#define G4    2048   // 4*HC

// ---- scratch (device globals: allocation-free rule) ----
__device__ float g_XG[(size_t)SEQT * BATCH * G4];   // [t][b][g]  input projections + biases
__device__ float g_WIT[KPAD * G4];                  // [k][g]     W_ih transposed, zero-padded K
__device__ float g_H[2][BATCH * HC];                // double-buffered hidden
__device__ float g_C[2][BATCH * HC];                // double-buffered cell

// d_out layout (concatenated, reference return order):
//   output      [B,T,HC]  at 0
//   cell_output [B,T,HC]  at 16777216
//   h           [B,HC]    at 33554432
//   c           [B,HC]    at 33587200
#define OUT_CELL_OFF  ((size_t)BATCH * SEQT * HC)
#define OUT_H_OFF     (2 * OUT_CELL_OFF)
#define OUT_C_OFF     (OUT_H_OFF + (size_t)BATCH * HC)

// ---------------------------------------------------------------------------
// W_ih [2048,300] -> g_WIT [304,2048]  (zero pad rows 300..303)
// ---------------------------------------------------------------------------
__global__ void transpose_wih(const float* __restrict__ W_ih) {
    __shared__ float tile[32][33];
    int n0 = blockIdx.x * 32;   // gate column block
    int k0 = blockIdx.y * 32;   // k block
    int tx = threadIdx.x;       // 0..31
    int ty = threadIdx.y;       // 0..7
#pragma unroll
    for (int i = 0; i < 32; i += 8) {
        int n = n0 + ty + i;
        int k = k0 + tx;
        tile[ty + i][tx] = (k < EDIM) ? W_ih[(size_t)n * EDIM + k] : 0.f;
    }
    __syncthreads();
#pragma unroll
    for (int i = 0; i < 32; i += 8) {
        int k = k0 + ty + i;
        int n = n0 + tx;
        if (k < KPAD) g_WIT[(size_t)k * G4 + n] = tile[tx][ty + i];
    }
}

__global__ void init_state() {
    int idx = blockIdx.x * 256 + threadIdx.x;   // 128 blocks -> 32768
    g_H[0][idx] = 0.f;
    g_C[0][idx] = 0.f;
}

// ---------------------------------------------------------------------------
// Input GEMM: XG[r][n] = emb[tok(r)] . WIT[:,n] + b_ih[n] + b_hh[n]
// r = t*64 + b, tok = seq[b*512 + t].  Tile 128x64x16, 256 thr, 8x4 microtile.
// ---------------------------------------------------------------------------
#define BM 128
#define BN 64
#define BK 16

__global__ void __launch_bounds__(256) embed_gemm(
    const int* __restrict__ seq,
    const float* __restrict__ emb,
    const float* __restrict__ b_ih,
    const float* __restrict__ b_hh)
{
    __shared__ float As[BK][BM + 4];
    __shared__ float Bs[BK][BN];
    __shared__ int   toks[BM];

    int tid  = threadIdx.x;          // 0..255
    int r0   = blockIdx.y * BM;      // row block (256 blocks)
    int n0   = blockIdx.x * BN;      // col block (32 blocks)

    if (tid < BM) {
        int r = r0 + tid;
        int b = r & 63;
        int t = r >> 6;
        toks[tid] = seq[b * SEQT + t];
    }
    __syncthreads();

    int tx = tid & 15;   // n quad
    int ty = tid >> 4;   // m octet

    float acc[8][4];
#pragma unroll
    for (int i = 0; i < 8; i++)
#pragma unroll
        for (int jn = 0; jn < 4; jn++) acc[i][jn] = 0.f;

    for (int kb = 0; kb < KPAD; kb += BK) {
        // A tile: 128 rows x 16 k (gather from embedding)
#pragma unroll
        for (int l = 0; l < 2; l++) {
            int fidx = tid + l * 256;          // 0..511 float4 slots
            int m    = fidx >> 2;              // 0..127
            int kq   = (fidx & 3) * 4;
            int k    = kb + kq;
            float4 v = make_float4(0.f, 0.f, 0.f, 0.f);
            if (k < EDIM)
                v = *(const float4*)(emb + (size_t)toks[m] * EDIM + k);
            As[kq + 0][m] = v.x;
            As[kq + 1][m] = v.y;
            As[kq + 2][m] = v.z;
            As[kq + 3][m] = v.w;
        }
        // B tile: 16 k x 64 n from WIT (coalesced)
        {
            int k  = tid >> 4;
            int nq = (tid & 15) * 4;
            float4 v = *(const float4*)(g_WIT + (size_t)(kb + k) * G4 + n0 + nq);
            *(float4*)&Bs[k][nq] = v;
        }
        __syncthreads();

#pragma unroll
        for (int k = 0; k < BK; k++) {
            float a0[4], a1[4], bv[4];
            *(float4*)a0 = *(const float4*)&As[k][ty * 8];
            *(float4*)a1 = *(const float4*)&As[k][ty * 8 + 4];
            *(float4*)bv = *(const float4*)&Bs[k][tx * 4];
#pragma unroll
            for (int i = 0; i < 4; i++)
#pragma unroll
                for (int jn = 0; jn < 4; jn++) {
                    acc[i][jn]     = fmaf(a0[i], bv[jn], acc[i][jn]);
                    acc[i + 4][jn] = fmaf(a1[i], bv[jn], acc[i + 4][jn]);
                }
        }
        __syncthreads();
    }

    int n = n0 + tx * 4;
    float4 bi = *(const float4*)(b_ih + n);
    float4 bh = *(const float4*)(b_hh + n);
    float4 bias = make_float4(bi.x + bh.x, bi.y + bh.y, bi.z + bh.z, bi.w + bh.w);

#pragma unroll
    for (int i = 0; i < 8; i++) {
        int r = r0 + ty * 8 + i;
        float4 o = make_float4(acc[i][0] + bias.x, acc[i][1] + bias.y,
                               acc[i][2] + bias.z, acc[i][3] + bias.w);
        *(float4*)(g_XG + (size_t)r * G4 + n) = o;
    }
}

// ---------------------------------------------------------------------------
// One LSTM step. 128 blocks x 256 threads. Thread owns (b, j): computes the
// 4 gate dot-products over K=512, then the pointwise update + masking.
// h staged via shared chunks of 32 k, prefetched into regs (sw pipeline).
// ---------------------------------------------------------------------------
__global__ void __launch_bounds__(256) lstm_step(
    const float* __restrict__ W_hh,
    const int*   __restrict__ lengths,
    int t,
    float* __restrict__ out)
{
    const float* xg   = g_XG + (size_t)t * (BATCH * G4);
    const float* h_in = g_H[t & 1];
    const float* c_in = g_C[t & 1];
    float* h_out = g_H[(t & 1) ^ 1];
    float* c_out = g_C[(t & 1) ^ 1];

    __shared__ float Hs[32][65];   // [kk][b], padded

    int tid = threadIdx.x;
    int jj  = tid & 3;
    int b   = tid >> 2;            // 0..63
    int j   = blockIdx.x * 4 + jj; // 0..511

    const float* Wi = W_hh + (size_t)(       j) * HC;
    const float* Wf = W_hh + (size_t)( 512 + j) * HC;
    const float* Wg = W_hh + (size_t)(1024 + j) * HC;
    const float* Wo = W_hh + (size_t)(1536 + j) * HC;

    float ai0 = 0.f, af0 = 0.f, ag0 = 0.f, ao0 = 0.f;
    float ai1 = 0.f, af1 = 0.f, ag1 = 0.f, ao1 = 0.f;

    float ld[8];
#pragma unroll
    for (int i = 0; i < 8; i++) {
        int idx = tid + i * 256;
        ld[i] = h_in[(idx >> 5) * HC + (idx & 31)];
    }

    for (int kb = 0; kb < HC; kb += 32) {
#pragma unroll
        for (int i = 0; i < 8; i++) {
            int idx = tid + i * 256;
            Hs[idx & 31][idx >> 5] = ld[i];
        }
        __syncthreads();

        if (kb + 32 < HC) {
#pragma unroll
            for (int i = 0; i < 8; i++) {
                int idx = tid + i * 256;
                ld[i] = h_in[(idx >> 5) * HC + kb + 32 + (idx & 31)];
            }
        }

#pragma unroll
        for (int kk = 0; kk < 32; kk += 8) {
            float4 wiA = *(const float4*)(Wi + kb + kk);
            float4 wfA = *(const float4*)(Wf + kb + kk);
            float4 wgA = *(const float4*)(Wg + kb + kk);
            float4 woA = *(const float4*)(Wo + kb + kk);
            float4 wiB = *(const float4*)(Wi + kb + kk + 4);
            float4 wfB = *(const float4*)(Wf + kb + kk + 4);
            float4 wgB = *(const float4*)(Wg + kb + kk + 4);
            float4 woB = *(const float4*)(Wo + kb + kk + 4);
            float h0 = Hs[kk + 0][b], h1 = Hs[kk + 1][b];
            float h2 = Hs[kk + 2][b], h3 = Hs[kk + 3][b];
            float h4 = Hs[kk + 4][b], h5 = Hs[kk + 5][b];
            float h6 = Hs[kk + 6][b], h7 = Hs[kk + 7][b];

            ai0 = fmaf(h0, wiA.x, ai0); ai0 = fmaf(h1, wiA.y, ai0);
            ai0 = fmaf(h2, wiA.z, ai0); ai0 = fmaf(h3, wiA.w, ai0);
            af0 = fmaf(h0, wfA.x, af0); af0 = fmaf(h1, wfA.y, af0);
            af0 = fmaf(h2, wfA.z, af0); af0 = fmaf(h3, wfA.w, af0);
            ag0 = fmaf(h0, wgA.x, ag0); ag0 = fmaf(h1, wgA.y, ag0);
            ag0 = fmaf(h2, wgA.z, ag0); ag0 = fmaf(h3, wgA.w, ag0);
            ao0 = fmaf(h0, woA.x, ao0); ao0 = fmaf(h1, woA.y, ao0);
            ao0 = fmaf(h2, woA.z, ao0); ao0 = fmaf(h3, woA.w, ao0);

            ai1 = fmaf(h4, wiB.x, ai1); ai1 = fmaf(h5, wiB.y, ai1);
            ai1 = fmaf(h6, wiB.z, ai1); ai1 = fmaf(h7, wiB.w, ai1);
            af1 = fmaf(h4, wfB.x, af1); af1 = fmaf(h5, wfB.y, af1);
            af1 = fmaf(h6, wfB.z, af1); af1 = fmaf(h7, wfB.w, af1);
            ag1 = fmaf(h4, wgB.x, ag1); ag1 = fmaf(h5, wgB.y, ag1);
            ag1 = fmaf(h6, wgB.z, ag1); ag1 = fmaf(h7, wgB.w, ag1);
            ao1 = fmaf(h4, woB.x, ao1); ao1 = fmaf(h5, woB.y, ao1);
            ao1 = fmaf(h6, woB.z, ao1); ao1 = fmaf(h7, woB.w, ao1);
        }
        __syncthreads();
    }

    float pi = xg[b * G4 +        j] + ai0 + ai1;
    float pf = xg[b * G4 +  512 + j] + af0 + af1;
    float pg = xg[b * G4 + 1024 + j] + ag0 + ag1;
    float po = xg[b * G4 + 1536 + j] + ao0 + ao1;

    float gi = 1.f / (1.f + expf(-pi));
    float gf = 1.f / (1.f + expf(-pf));
    float gg = tanhf(pg);
    float go = 1.f / (1.f + expf(-po));

    float cprev = c_in[b * HC + j];
    float cn = gf * cprev + gi * gg;
    float hn = go * tanhf(cn);

    int m = (t < lengths[b]);
    float hv = m ? hn : h_in[b * HC + j];
    float cv = m ? cn : cprev;

    h_out[b * HC + j] = hv;
    c_out[b * HC + j] = cv;

    size_t o = (size_t)b * (SEQT * HC) + (size_t)t * HC + j;
    out[o]                = m ? hn : 0.f;
    out[OUT_CELL_OFF + o] = m ? cn : 0.f;
}

__global__ void final_copy(float* __restrict__ out) {
    int idx = blockIdx.x * 256 + threadIdx.x;   // 128 blocks -> 32768
    out[OUT_H_OFF + idx] = g_H[0][idx];
    out[OUT_C_OFF + idx] = g_C[0][idx];
}

// ---------------------------------------------------------------------------
extern "C" void kernel_launch(void* const* d_in, const int* in_sizes, int n_in,
                              void* d_out, int out_size) {
    const int*   seq     = (const int*)d_in[0];
    const int*   lengths = (const int*)d_in[1];
    const float* emb     = (const float*)d_in[2];
    const float* W_ih    = (const float*)d_in[3];
    const float* W_hh    = (const float*)d_in[4];
    const float* b_ih    = (const float*)d_in[5];
    const float* b_hh    = (const float*)d_in[6];
    float* out = (float*)d_out;

    transpose_wih<<<dim3(64, 10), dim3(32, 8)>>>(W_ih);
    init_state<<<128, 256>>>();
    embed_gemm<<<dim3(32, 256), 256>>>(seq, emb, b_ih, b_hh);

    for (int t = 0; t < SEQT; t++)
        lstm_step<<<128, 256>>>(W_hh, lengths, t, out);

    final_copy<<<128, 256>>>(out);
}

// round 2
// speedup vs baseline: 1.2389x; 1.2389x over previous
#include <cuda_runtime.h>
#include <math.h>
#include <stdint.h>

#define BATCH 64
#define SEQT  512
#define EDIM  300
#define KPAD  304
#define HC    512
#define G4    2048   // 4*HC
#define NBLK  128

typedef unsigned long long ull;

// ---- scratch (device globals: allocation-free rule) ----
__device__ float g_XG[(size_t)SEQT * BATCH * G4];   // [t][b][g]  input projections + biases
__device__ float g_WIT[KPAD * G4];                  // [k][g]     W_ih transposed, zero-padded K
__device__ float g_H[2][BATCH * HC];                // double-buffered hidden (published)
__device__ unsigned int          g_count;           // barrier arrival counter
__device__ volatile unsigned int g_epoch;           // barrier epoch

#define OUT_CELL_OFF  ((size_t)BATCH * SEQT * HC)
#define OUT_H_OFF     (2 * OUT_CELL_OFF)
#define OUT_C_OFF     (OUT_H_OFF + (size_t)BATCH * HC)

// ---------------- packed fp32x2 helpers (sm_100+) ----------------
__device__ __forceinline__ ull ffma2(ull a, ull b, ull c) {
    ull d;
    asm("fma.rn.f32x2 %0, %1, %2, %3;" : "=l"(d) : "l"(a), "l"(b), "l"(c));
    return d;
}
__device__ __forceinline__ ull pk2(float x, float y) {
    ull r;
    asm("mov.b64 %0, {%1, %2};" : "=l"(r)
        : "r"(__float_as_uint(x)), "r"(__float_as_uint(y)));
    return r;
}
__device__ __forceinline__ float hsum2(ull v) {
    unsigned a, b;
    asm("mov.b64 {%0, %1}, %2;" : "=r"(a), "=r"(b) : "l"(v));
    return __uint_as_float(a) + __uint_as_float(b);
}
__device__ __forceinline__ void unpk2(ull v, float& x, float& y) {
    unsigned a, b;
    asm("mov.b64 {%0, %1}, %2;" : "=r"(a), "=r"(b) : "l"(v));
    x = __uint_as_float(a); y = __uint_as_float(b);
}

// ---------------------------------------------------------------------------
// W_ih [2048,300] -> g_WIT [304,2048]  (zero pad rows 300..303)
// ---------------------------------------------------------------------------
__global__ void transpose_wih(const float* __restrict__ W_ih) {
    __shared__ float tile[32][33];
    int n0 = blockIdx.x * 32;
    int k0 = blockIdx.y * 32;
    int tx = threadIdx.x;
    int ty = threadIdx.y;
#pragma unroll
    for (int i = 0; i < 32; i += 8) {
        int n = n0 + ty + i;
        int k = k0 + tx;
        tile[ty + i][tx] = (k < EDIM) ? W_ih[(size_t)n * EDIM + k] : 0.f;
    }
    __syncthreads();
#pragma unroll
    for (int i = 0; i < 32; i += 8) {
        int k = k0 + ty + i;
        int n = n0 + tx;
        if (k < KPAD) g_WIT[(size_t)k * G4 + n] = tile[tx][ty + i];
    }
}

// ---------------------------------------------------------------------------
// Input GEMM: XG[r][n] = emb[tok(r)] . WIT[:,n] + b_ih[n] + b_hh[n]
// r = t*64 + b. Tile 128x64x16, 256 thr, 8x4 microtile, f32x2 accumulators.
// ---------------------------------------------------------------------------
#define BM 128
#define BN 64
#define BK 16

__global__ void __launch_bounds__(256) embed_gemm(
    const int* __restrict__ seq,
    const float* __restrict__ emb,
    const float* __restrict__ b_ih,
    const float* __restrict__ b_hh)
{
    __shared__ float As[BK][BM + 4];
    __shared__ float Bs[BK][BN];
    __shared__ int   toks[BM];

    int tid = threadIdx.x;
    int r0  = blockIdx.y * BM;
    int n0  = blockIdx.x * BN;

    if (tid < BM) {
        int r = r0 + tid;
        int b = r & 63;
        int t = r >> 6;
        toks[tid] = seq[b * SEQT + t];
    }
    __syncthreads();

    int tx = tid & 15;   // n quad
    int ty = tid >> 4;   // m octet

    ull acc[8][2];
#pragma unroll
    for (int i = 0; i < 8; i++) { acc[i][0] = 0ull; acc[i][1] = 0ull; }

    for (int kb = 0; kb < KPAD; kb += BK) {
#pragma unroll
        for (int l = 0; l < 2; l++) {
            int fidx = tid + l * 256;
            int m    = fidx >> 2;
            int kq   = (fidx & 3) * 4;
            int k    = kb + kq;
            float4 v = make_float4(0.f, 0.f, 0.f, 0.f);
            if (k < EDIM)
                v = *(const float4*)(emb + (size_t)toks[m] * EDIM + k);
            As[kq + 0][m] = v.x;
            As[kq + 1][m] = v.y;
            As[kq + 2][m] = v.z;
            As[kq + 3][m] = v.w;
        }
        {
            int k  = tid >> 4;
            int nq = (tid & 15) * 4;
            float4 v = *(const float4*)(g_WIT + (size_t)(kb + k) * G4 + n0 + nq);
            *(float4*)&Bs[k][nq] = v;
        }
        __syncthreads();

#pragma unroll
        for (int k = 0; k < BK; k++) {
            ull b01 = *(const ull*)&Bs[k][tx * 4];
            ull b23 = *(const ull*)&Bs[k][tx * 4 + 2];
            float a0[4], a1[4];
            *(float4*)a0 = *(const float4*)&As[k][ty * 8];
            *(float4*)a1 = *(const float4*)&As[k][ty * 8 + 4];
#pragma unroll
            for (int i = 0; i < 4; i++) {
                ull aaA = pk2(a0[i], a0[i]);
                ull aaB = pk2(a1[i], a1[i]);
                acc[i][0]     = ffma2(aaA, b01, acc[i][0]);
                acc[i][1]     = ffma2(aaA, b23, acc[i][1]);
                acc[i + 4][0] = ffma2(aaB, b01, acc[i + 4][0]);
                acc[i + 4][1] = ffma2(aaB, b23, acc[i + 4][1]);
            }
        }
        __syncthreads();
    }

    int n = n0 + tx * 4;
    float4 bi = *(const float4*)(b_ih + n);
    float4 bh = *(const float4*)(b_hh + n);

#pragma unroll
    for (int i = 0; i < 8; i++) {
        int r = r0 + ty * 8 + i;
        float x, y, z, w;
        unpk2(acc[i][0], x, y);
        unpk2(acc[i][1], z, w);
        float4 o = make_float4(x + bi.x + bh.x, y + bi.y + bh.y,
                               z + bi.z + bh.z, w + bi.w + bh.w);
        *(float4*)(g_XG + (size_t)r * G4 + n) = o;
    }
}

// ---------------------------------------------------------------------------
// Global barrier (128 co-resident blocks). __threadfence() emits CCTL.IVALL
// on sm_103a, which also invalidates L1 so next step's h reads are coherent.
// ---------------------------------------------------------------------------
__device__ __forceinline__ void gbar() {
    __syncthreads();
    if (threadIdx.x == 0) {
        unsigned int my = g_epoch;
        __threadfence();
        if (atomicAdd(&g_count, 1) == NBLK - 1) {
            g_count = 0;
            __threadfence();
            g_epoch = my + 1;
        } else {
            while (g_epoch == my) { }
        }
        __threadfence();
    }
    __syncthreads();
}

// ---------------------------------------------------------------------------
// Persistent LSTM recurrence. 128 blocks x 256 threads.
// Block bk owns j in [4bk, 4bk+4) for all 4 gates = 16 W_hh rows, held in
// registers: thread = (bg, w2, rp_lo, kc) -> 2 rows x 64 k slice (128 regs).
// Per step: f32x2 dot products over 16 batches, bfly-reduce over 8 kc lanes,
// exchange via smem, fused pointwise LSTM update with register-resident h,c.
// ---------------------------------------------------------------------------
__global__ void __launch_bounds__(256) lstm_persistent(
    const float* __restrict__ W_hh,
    const int*   __restrict__ lengths,
    float* __restrict__ out)
{
    __shared__ float Ex[16 * 68];   // [local row][b], pitch 68 (conflict-free)

    const int tid  = threadIdx.x;
    const int bk   = blockIdx.x;

    const int bg    = tid >> 6;         // 0..3 : b group of 16
    const int lane  = tid & 31;
    const int w2    = (tid >> 5) & 1;
    const int rp_lo = lane >> 3;        // 0..3
    const int kc    = lane & 7;         // 0..7 : k chunk of 64
    const int rp    = w2 * 4 + rp_lo;   // 0..7 : row pair
    const int lr0   = 2 * rp;
    const int lr1   = 2 * rp + 1;
    // local row lr -> gate = lr>>2, jj = lr&3 -> W_hh row = gate*512 + 4bk + jj
    const int row0 = ((lr0 >> 2) << 9) + 4 * bk + (lr0 & 3);
    const int row1 = ((lr1 >> 2) << 9) + 4 * bk + (lr1 & 3);

    // --- load this thread's W slice into registers (stays for all 512 steps)
    ull W0[32], W1[32];
    {
        const ulonglong2* p0 = (const ulonglong2*)(W_hh + (size_t)row0 * HC + kc * 64);
        const ulonglong2* p1 = (const ulonglong2*)(W_hh + (size_t)row1 * HC + kc * 64);
#pragma unroll
        for (int i = 0; i < 16; i++) { ulonglong2 v = p0[i]; W0[2*i] = v.x; W0[2*i+1] = v.y; }
#pragma unroll
        for (int i = 0; i < 16; i++) { ulonglong2 v = p1[i]; W1[2*i] = v.x; W1[2*i+1] = v.y; }
    }

    // --- init published h buffer (parity 0)
    {
        int e = bk * 256 + tid;
        g_H[0][e] = 0.f;
    }

    // --- pointwise identity: this thread owns (b_pt, j_pt) forever
    const int jj   = tid & 3;
    const int b_pt = tid >> 2;          // 0..63
    const int j_pt = 4 * bk + jj;
    const int len_b = lengths[b_pt];
    float h_st = 0.f, c_st = 0.f;       // register-resident state

    gbar();

    for (int t = 0; t < SEQT; t++) {
        const int p = t & 1;
        const float* h_in = g_H[p];

        // ---- recurrence GEMV slice ----
        for (int bb = 0; bb < 16; bb++) {
            int b = bg * 16 + bb;
            const ulonglong2* hb =
                (const ulonglong2*)(h_in + (b << 9) + (kc << 6));
            ull a0 = 0ull, a1 = 0ull;
#pragma unroll
            for (int i = 0; i < 16; i++) {
                ulonglong2 hv = hb[i];
                a0 = ffma2(W0[2*i],     hv.x, a0);
                a0 = ffma2(W0[2*i + 1], hv.y, a0);
                a1 = ffma2(W1[2*i],     hv.x, a1);
                a1 = ffma2(W1[2*i + 1], hv.y, a1);
            }
            float s0 = hsum2(a0);
            float s1 = hsum2(a1);
            s0 += __shfl_xor_sync(0xffffffffu, s0, 1);
            s0 += __shfl_xor_sync(0xffffffffu, s0, 2);
            s0 += __shfl_xor_sync(0xffffffffu, s0, 4);
            s1 += __shfl_xor_sync(0xffffffffu, s1, 1);
            s1 += __shfl_xor_sync(0xffffffffu, s1, 2);
            s1 += __shfl_xor_sync(0xffffffffu, s1, 4);
            if (kc == 0) {
                Ex[lr0 * 68 + b] = s0;
                Ex[lr1 * 68 + b] = s1;
            }
        }
        __syncthreads();

        // ---- pointwise LSTM update ----
        {
            const float* xg = g_XG + (size_t)t * (BATCH * G4) + (size_t)b_pt * G4;
            float pi = xg[j_pt]        + Ex[(0  + jj) * 68 + b_pt];
            float pf = xg[512 + j_pt]  + Ex[(4  + jj) * 68 + b_pt];
            float pg = xg[1024 + j_pt] + Ex[(8  + jj) * 68 + b_pt];
            float po = xg[1536 + j_pt] + Ex[(12 + jj) * 68 + b_pt];

            float gi = 1.f / (1.f + expf(-pi));
            float gf = 1.f / (1.f + expf(-pf));
            float gg = tanhf(pg);
            float go = 1.f / (1.f + expf(-po));

            float cn = gf * c_st + gi * gg;
            float hn = go * tanhf(cn);

            bool m = (t < len_b);
            if (m) { c_st = cn; h_st = hn; }
            g_H[p ^ 1][(b_pt << 9) + j_pt] = h_st;

            size_t o = (size_t)b_pt * (SEQT * HC) + (size_t)t * HC + j_pt;
            out[o]                = m ? hn : 0.f;
            out[OUT_CELL_OFF + o] = m ? cn : 0.f;
        }
        gbar();
    }

    // ---- final h, c (register state is exactly the reference's h, c) ----
    {
        size_t e = (size_t)b_pt * HC + j_pt;
        out[OUT_H_OFF + e] = h_st;
        out[OUT_C_OFF + e] = c_st;
    }
}

// ---------------------------------------------------------------------------
extern "C" void kernel_launch(void* const* d_in, const int* in_sizes, int n_in,
                              void* d_out, int out_size) {
    const int*   seq     = (const int*)d_in[0];
    const int*   lengths = (const int*)d_in[1];
    const float* emb     = (const float*)d_in[2];
    const float* W_ih    = (const float*)d_in[3];
    const float* W_hh    = (const float*)d_in[4];
    const float* b_ih    = (const float*)d_in[5];
    const float* b_hh    = (const float*)d_in[6];
    float* out = (float*)d_out;

    transpose_wih<<<dim3(64, 10), dim3(32, 8)>>>(W_ih);
    embed_gemm<<<dim3(32, 256), 256>>>(seq, emb, b_ih, b_hh);
    lstm_persistent<<<NBLK, 256>>>(W_hh, lengths, out);
}

// round 3
// speedup vs baseline: 3.9542x; 3.1917x over previous
#include <cuda_runtime.h>
#include <math.h>
#include <stdint.h>

#define BATCH 64
#define SEQT  512
#define EDIM  300
#define KPAD  304
#define HC    512
#define G4    2048   // 4*HC
#define NBLK  128

typedef unsigned long long ull;

// ---- scratch (device globals: allocation-free rule) ----
__device__ float g_XG[(size_t)SEQT * BATCH * G4];   // [t][b][g]
__device__ float g_WIT[KPAD * G4];                  // [k][g]
__device__ float g_H[2][BATCH * HC];                // double-buffered hidden (L2-scope)
__device__ unsigned int g_count;                    // barrier counter (self-resetting)
__device__ unsigned int g_epoch;                    // barrier epoch (monotonic)

#define OUT_CELL_OFF  ((size_t)BATCH * SEQT * HC)
#define OUT_H_OFF     (2 * OUT_CELL_OFF)
#define OUT_C_OFF     (OUT_H_OFF + (size_t)BATCH * HC)

// ---------------- packed fp32x2 helpers (sm_100+) ----------------
__device__ __forceinline__ ull ffma2(ull a, ull b, ull c) {
    ull d;
    asm("fma.rn.f32x2 %0, %1, %2, %3;" : "=l"(d) : "l"(a), "l"(b), "l"(c));
    return d;
}
__device__ __forceinline__ ull pk2(float x, float y) {
    ull r;
    asm("mov.b64 %0, {%1, %2};" : "=l"(r)
        : "r"(__float_as_uint(x)), "r"(__float_as_uint(y)));
    return r;
}
__device__ __forceinline__ float hsum2(ull v) {
    unsigned a, b;
    asm("mov.b64 {%0, %1}, %2;" : "=r"(a), "=r"(b) : "l"(v));
    return __uint_as_float(a) + __uint_as_float(b);
}
__device__ __forceinline__ void unpk2(ull v, float& x, float& y) {
    unsigned a, b;
    asm("mov.b64 {%0, %1}, %2;" : "=r"(a), "=r"(b) : "l"(v));
    x = __uint_as_float(a); y = __uint_as_float(b);
}

// ---------------- L2-scope (.cg) accessors ----------------
__device__ __forceinline__ void ldcg_u64x2(const float* p, ull& x, ull& y) {
    asm volatile("ld.global.cg.v2.u64 {%0,%1}, [%2];"
                 : "=l"(x), "=l"(y) : "l"(p));
}
__device__ __forceinline__ float ldcg_f(const float* p) {
    float v;
    asm volatile("ld.global.cg.f32 %0, [%1];" : "=f"(v) : "l"(p));
    return v;
}
__device__ __forceinline__ void stcg_f(float* p, float v) {
    asm volatile("st.global.cg.f32 [%0], %1;" :: "l"(p), "f"(v));
}

// ---------------- scoped-atomic barrier primitives ----------------
__device__ __forceinline__ unsigned ld_acq(const unsigned* p) {
    unsigned v;
    asm volatile("ld.acquire.gpu.global.u32 %0, [%1];" : "=r"(v) : "l"(p) : "memory");
    return v;
}
__device__ __forceinline__ void st_rel(unsigned* p, unsigned v) {
    asm volatile("st.release.gpu.global.u32 [%0], %1;" :: "l"(p), "r"(v) : "memory");
}
__device__ __forceinline__ unsigned atom_add_rel(unsigned* p, unsigned v) {
    unsigned old;
    asm volatile("atom.release.gpu.global.add.u32 %0, [%1], %2;"
                 : "=r"(old) : "l"(p), "r"(v) : "memory");
    return old;
}

// ---------------------------------------------------------------------------
// W_ih [2048,300] -> g_WIT [304,2048]
// ---------------------------------------------------------------------------
__global__ void transpose_wih(const float* __restrict__ W_ih) {
    __shared__ float tile[32][33];
    int n0 = blockIdx.x * 32;
    int k0 = blockIdx.y * 32;
    int tx = threadIdx.x;
    int ty = threadIdx.y;
#pragma unroll
    for (int i = 0; i < 32; i += 8) {
        int n = n0 + ty + i;
        int k = k0 + tx;
        tile[ty + i][tx] = (k < EDIM) ? W_ih[(size_t)n * EDIM + k] : 0.f;
    }
    __syncthreads();
#pragma unroll
    for (int i = 0; i < 32; i += 8) {
        int k = k0 + ty + i;
        int n = n0 + tx;
        if (k < KPAD) g_WIT[(size_t)k * G4 + n] = tile[tx][ty + i];
    }
}

// ---------------------------------------------------------------------------
// Input GEMM: XG[r][n] = emb[tok(r)] . WIT[:,n] + b_ih[n] + b_hh[n]
// ---------------------------------------------------------------------------
#define BM 128
#define BN 64
#define BK 16

__global__ void __launch_bounds__(256) embed_gemm(
    const int* __restrict__ seq,
    const float* __restrict__ emb,
    const float* __restrict__ b_ih,
    const float* __restrict__ b_hh)
{
    __shared__ float As[BK][BM + 4];
    __shared__ float Bs[BK][BN];
    __shared__ int   toks[BM];

    int tid = threadIdx.x;
    int r0  = blockIdx.y * BM;
    int n0  = blockIdx.x * BN;

    if (tid < BM) {
        int r = r0 + tid;
        int b = r & 63;
        int t = r >> 6;
        toks[tid] = seq[b * SEQT + t];
    }
    __syncthreads();

    int tx = tid & 15;
    int ty = tid >> 4;

    ull acc[8][2];
#pragma unroll
    for (int i = 0; i < 8; i++) { acc[i][0] = 0ull; acc[i][1] = 0ull; }

    for (int kb = 0; kb < KPAD; kb += BK) {
#pragma unroll
        for (int l = 0; l < 2; l++) {
            int fidx = tid + l * 256;
            int m    = fidx >> 2;
            int kq   = (fidx & 3) * 4;
            int k    = kb + kq;
            float4 v = make_float4(0.f, 0.f, 0.f, 0.f);
            if (k < EDIM)
                v = *(const float4*)(emb + (size_t)toks[m] * EDIM + k);
            As[kq + 0][m] = v.x;
            As[kq + 1][m] = v.y;
            As[kq + 2][m] = v.z;
            As[kq + 3][m] = v.w;
        }
        {
            int k  = tid >> 4;
            int nq = (tid & 15) * 4;
            float4 v = *(const float4*)(g_WIT + (size_t)(kb + k) * G4 + n0 + nq);
            *(float4*)&Bs[k][nq] = v;
        }
        __syncthreads();

#pragma unroll
        for (int k = 0; k < BK; k++) {
            ull b01 = *(const ull*)&Bs[k][tx * 4];
            ull b23 = *(const ull*)&Bs[k][tx * 4 + 2];
            float a0[4], a1[4];
            *(float4*)a0 = *(const float4*)&As[k][ty * 8];
            *(float4*)a1 = *(const float4*)&As[k][ty * 8 + 4];
#pragma unroll
            for (int i = 0; i < 4; i++) {
                ull aaA = pk2(a0[i], a0[i]);
                ull aaB = pk2(a1[i], a1[i]);
                acc[i][0]     = ffma2(aaA, b01, acc[i][0]);
                acc[i][1]     = ffma2(aaA, b23, acc[i][1]);
                acc[i + 4][0] = ffma2(aaB, b01, acc[i + 4][0]);
                acc[i + 4][1] = ffma2(aaB, b23, acc[i + 4][1]);
            }
        }
        __syncthreads();
    }

    int n = n0 + tx * 4;
    float4 bi = *(const float4*)(b_ih + n);
    float4 bh = *(const float4*)(b_hh + n);

#pragma unroll
    for (int i = 0; i < 8; i++) {
        int r = r0 + ty * 8 + i;
        float x, y, z, w;
        unpk2(acc[i][0], x, y);
        unpk2(acc[i][1], z, w);
        float4 o = make_float4(x + bi.x + bh.x, y + bi.y + bh.y,
                               z + bi.z + bh.z, w + bi.w + bh.w);
        *(float4*)(g_XG + (size_t)r * G4 + n) = o;
    }
}

// ---------------------------------------------------------------------------
// Global barrier: release-add + acquire-spin (no CCTL.IVALL; all shared data
// uses .cg so L1 never holds stale cross-block state). Self-restoring.
// ---------------------------------------------------------------------------
__device__ __forceinline__ void gbar() {
    __syncthreads();
    if (threadIdx.x == 0) {
        unsigned my = ld_acq(&g_epoch);
        unsigned prev = atom_add_rel(&g_count, 1);
        if (prev == NBLK - 1) {
            g_count = 0;               // plain store, ordered by release below
            st_rel(&g_epoch, my + 1);
        } else {
            while (ld_acq(&g_epoch) == my) { }
        }
    }
    __syncthreads();
}

// ---------------------------------------------------------------------------
// Persistent LSTM recurrence. 128 blocks x 256 threads.
// warp w: rg = w&1 (row group of 8), bgrp = w>>1 (16 batches).
// lane: kc = lane&7 (k interleave), rp = lane>>3 (row pair within rg).
// Thread k-slice: {m*32 + kc*4 + q} -> warp LDG.128 touches ONE 128B line.
// W_hh slice (2 rows x 64 k) register-resident for all 512 steps.
// ---------------------------------------------------------------------------
__global__ void __launch_bounds__(256, 1) lstm_persistent(
    const float* __restrict__ W_hh,
    const int*   __restrict__ lengths,
    float* __restrict__ out)
{
    __shared__ float Ex[16 * 69];   // [lr][b], pitch 69

    const int tid  = threadIdx.x;
    const int bk   = blockIdx.x;
    const int lane = tid & 31;
    const int w    = tid >> 5;
    const int rg   = w & 1;
    const int bgrp = w >> 1;        // 0..3
    const int kc   = lane & 7;
    const int rp   = lane >> 3;     // 0..3

    const int lr0 = rg * 8 + rp * 2;
    const int lr1 = lr0 + 1;
    // lr = gate*4 + jj  ->  W_hh row = gate*512 + 4*bk + jj
    const int row0 = ((lr0 >> 2) << 9) + 4 * bk + (lr0 & 3);
    const int row1 = ((lr1 >> 2) << 9) + 4 * bk + (lr1 & 3);

    // --- W slice into registers: W[2m],W[2m+1] cover k = m*32 + kc*4 .. +3
    ull W0[32], W1[32];
#pragma unroll
    for (int m = 0; m < 16; m++) {
        const float* p0 = W_hh + (size_t)row0 * HC + m * 32 + kc * 4;
        const float* p1 = W_hh + (size_t)row1 * HC + m * 32 + kc * 4;
        ulonglong2 v0 = *(const ulonglong2*)p0;
        ulonglong2 v1 = *(const ulonglong2*)p1;
        W0[2 * m] = v0.x; W0[2 * m + 1] = v0.y;
        W1[2 * m] = v1.x; W1[2 * m + 1] = v1.y;
    }

    // --- init published h (parity 0) via .cg
    stcg_f(&g_H[0][bk * 256 + tid], 0.f);

    // --- pointwise identity
    const int jj   = tid & 3;
    const int b_pt = tid >> 2;
    const int j_pt = 4 * bk + jj;
    const int len_b = lengths[b_pt];
    float h_st = 0.f, c_st = 0.f;

    gbar();

    for (int t = 0; t < SEQT; t++) {
        const int p = t & 1;
        const float* h_in = g_H[p];

        // prefetch this step's xg (DRAM) so latency hides under the GEMV
        const float* xg = g_XG + (size_t)t * (BATCH * G4) + (size_t)b_pt * G4;
        float xi = ldcg_f(xg + j_pt);
        float xf = ldcg_f(xg + 512 + j_pt);
        float xg_ = ldcg_f(xg + 1024 + j_pt);
        float xo = ldcg_f(xg + 1536 + j_pt);

        // ---- recurrence GEMV slice ----
#pragma unroll 1
        for (int bb = 0; bb < 16; bb++) {
            const int b = bgrp * 16 + bb;
            const float* hb = h_in + (b << 9) + (kc << 2);

            ull a0 = 0ull, a1 = 0ull;
#pragma unroll
            for (int half = 0; half < 2; half++) {
                ull hx[16];
#pragma unroll
                for (int m = 0; m < 8; m++)
                    ldcg_u64x2(hb + ((half * 8 + m) << 5), hx[2 * m], hx[2 * m + 1]);
#pragma unroll
                for (int m = 0; m < 8; m++) {
                    int mm = half * 16 + 2 * m;
                    a0 = ffma2(W0[mm],     hx[2 * m],     a0);
                    a0 = ffma2(W0[mm + 1], hx[2 * m + 1], a0);
                    a1 = ffma2(W1[mm],     hx[2 * m],     a1);
                    a1 = ffma2(W1[mm + 1], hx[2 * m + 1], a1);
                }
            }
            float s0 = hsum2(a0);
            float s1 = hsum2(a1);
            s0 += __shfl_xor_sync(0xffffffffu, s0, 1);
            s0 += __shfl_xor_sync(0xffffffffu, s0, 2);
            s0 += __shfl_xor_sync(0xffffffffu, s0, 4);
            s1 += __shfl_xor_sync(0xffffffffu, s1, 1);
            s1 += __shfl_xor_sync(0xffffffffu, s1, 2);
            s1 += __shfl_xor_sync(0xffffffffu, s1, 4);
            if (kc == 0) {
                Ex[lr0 * 69 + b] = s0;
                Ex[lr1 * 69 + b] = s1;
            }
        }
        __syncthreads();

        // ---- pointwise LSTM update ----
        {
            float pi = xi  + Ex[(0  + jj) * 69 + b_pt];
            float pf = xf  + Ex[(4  + jj) * 69 + b_pt];
            float pg = xg_ + Ex[(8  + jj) * 69 + b_pt];
            float po = xo  + Ex[(12 + jj) * 69 + b_pt];

            float gi = 1.f / (1.f + expf(-pi));
            float gf = 1.f / (1.f + expf(-pf));
            float gg = tanhf(pg);
            float go = 1.f / (1.f + expf(-po));

            float cn = gf * c_st + gi * gg;
            float hn = go * tanhf(cn);

            bool msk = (t < len_b);
            if (msk) { c_st = cn; h_st = hn; }
            stcg_f(&g_H[p ^ 1][(b_pt << 9) + j_pt], h_st);

            size_t o = (size_t)b_pt * (SEQT * HC) + (size_t)t * HC + j_pt;
            out[o]                = msk ? hn : 0.f;
            out[OUT_CELL_OFF + o] = msk ? cn : 0.f;
        }
        gbar();
    }

    // ---- final h, c ----
    {
        size_t e = (size_t)b_pt * HC + j_pt;
        out[OUT_H_OFF + e] = h_st;
        out[OUT_C_OFF + e] = c_st;
    }
}

// ---------------------------------------------------------------------------
extern "C" void kernel_launch(void* const* d_in, const int* in_sizes, int n_in,
                              void* d_out, int out_size) {
    const int*   seq     = (const int*)d_in[0];
    const int*   lengths = (const int*)d_in[1];
    const float* emb     = (const float*)d_in[2];
    const float* W_ih    = (const float*)d_in[3];
    const float* W_hh    = (const float*)d_in[4];
    const float* b_ih    = (const float*)d_in[5];
    const float* b_hh    = (const float*)d_in[6];
    float* out = (float*)d_out;

    transpose_wih<<<dim3(64, 10), dim3(32, 8)>>>(W_ih);
    embed_gemm<<<dim3(32, 256), 256>>>(seq, emb, b_ih, b_hh);
    lstm_persistent<<<NBLK, 256>>>(W_hh, lengths, out);
}

// round 4
// speedup vs baseline: 4.1569x; 1.0513x over previous
#include <cuda_runtime.h>
#include <math.h>
#include <stdint.h>

#define BATCH 64
#define SEQT  512
#define EDIM  300
#define KPAD  304
#define HC    512
#define G4    2048   // 4*HC
#define NBLK  128

typedef unsigned long long ull;

// ---- scratch (device globals: allocation-free rule) ----
__device__ float g_XG[(size_t)SEQT * BATCH * G4];   // [t][b][g]
__device__ float g_WIT[KPAD * G4];                  // [k][g]
__device__ float g_H[2][BATCH * HC];                // double-buffered hidden (L2-scope)
__device__ unsigned int g_count;                    // barrier counter (self-resetting)
__device__ unsigned int g_epoch;                    // barrier epoch (monotonic)

#define OUT_CELL_OFF  ((size_t)BATCH * SEQT * HC)
#define OUT_H_OFF     (2 * OUT_CELL_OFF)
#define OUT_C_OFF     (OUT_H_OFF + (size_t)BATCH * HC)

// ---------------- packed fp32x2 helpers (sm_100+) ----------------
__device__ __forceinline__ ull ffma2(ull a, ull b, ull c) {
    ull d;
    asm("fma.rn.f32x2 %0, %1, %2, %3;" : "=l"(d) : "l"(a), "l"(b), "l"(c));
    return d;
}
__device__ __forceinline__ ull pk2(float x, float y) {
    ull r;
    asm("mov.b64 %0, {%1, %2};" : "=l"(r)
        : "r"(__float_as_uint(x)), "r"(__float_as_uint(y)));
    return r;
}
__device__ __forceinline__ float hsum2(ull v) {
    unsigned a, b;
    asm("mov.b64 {%0, %1}, %2;" : "=r"(a), "=r"(b) : "l"(v));
    return __uint_as_float(a) + __uint_as_float(b);
}
__device__ __forceinline__ void unpk2(ull v, float& x, float& y) {
    unsigned a, b;
    asm("mov.b64 {%0, %1}, %2;" : "=r"(a), "=r"(b) : "l"(v));
    x = __uint_as_float(a); y = __uint_as_float(b);
}

// ---------------- L2-scope (.cg) accessors ----------------
__device__ __forceinline__ void ldcg_u64x2(const float* p, ull& x, ull& y) {
    asm volatile("ld.global.cg.v2.u64 {%0,%1}, [%2];"
                 : "=l"(x), "=l"(y) : "l"(p));
}
__device__ __forceinline__ float ldcg_f(const float* p) {
    float v;
    asm volatile("ld.global.cg.f32 %0, [%1];" : "=f"(v) : "l"(p));
    return v;
}
__device__ __forceinline__ void stcg_f(float* p, float v) {
    asm volatile("st.global.cg.f32 [%0], %1;" :: "l"(p), "f"(v));
}

// ---------------- scoped-atomic barrier primitives ----------------
__device__ __forceinline__ unsigned ld_acq(const unsigned* p) {
    unsigned v;
    asm volatile("ld.acquire.gpu.global.u32 %0, [%1];" : "=r"(v) : "l"(p) : "memory");
    return v;
}
__device__ __forceinline__ void st_rel(unsigned* p, unsigned v) {
    asm volatile("st.release.gpu.global.u32 [%0], %1;" :: "l"(p), "r"(v) : "memory");
}
__device__ __forceinline__ unsigned atom_add_rel(unsigned* p, unsigned v) {
    unsigned old;
    asm volatile("atom.release.gpu.global.add.u32 %0, [%1], %2;"
                 : "=r"(old) : "l"(p), "r"(v) : "memory");
    return old;
}
// split-phase barrier (thread 0 only); target = e0 + barrier_index
__device__ __forceinline__ void bar_arrive(unsigned target) {
    if (atom_add_rel(&g_count, 1) == NBLK - 1) {
        g_count = 0;                 // ordered before epoch by release below
        st_rel(&g_epoch, target);
    }
}
__device__ __forceinline__ void bar_wait(unsigned target) {
    while (ld_acq(&g_epoch) != target) { }
}

// ---------------------------------------------------------------------------
// W_ih [2048,300] -> g_WIT [304,2048]
// ---------------------------------------------------------------------------
__global__ void transpose_wih(const float* __restrict__ W_ih) {
    __shared__ float tile[32][33];
    int n0 = blockIdx.x * 32;
    int k0 = blockIdx.y * 32;
    int tx = threadIdx.x;
    int ty = threadIdx.y;
#pragma unroll
    for (int i = 0; i < 32; i += 8) {
        int n = n0 + ty + i;
        int k = k0 + tx;
        tile[ty + i][tx] = (k < EDIM) ? W_ih[(size_t)n * EDIM + k] : 0.f;
    }
    __syncthreads();
#pragma unroll
    for (int i = 0; i < 32; i += 8) {
        int k = k0 + ty + i;
        int n = n0 + tx;
        if (k < KPAD) g_WIT[(size_t)k * G4 + n] = tile[tx][ty + i];
    }
}

// ---------------------------------------------------------------------------
// Input GEMM: XG[r][n] = emb[tok(r)] . WIT[:,n] + b_ih[n] + b_hh[n]
// ---------------------------------------------------------------------------
#define BM 128
#define BN 64
#define BK 16

__global__ void __launch_bounds__(256) embed_gemm(
    const int* __restrict__ seq,
    const float* __restrict__ emb,
    const float* __restrict__ b_ih,
    const float* __restrict__ b_hh)
{
    __shared__ float As[BK][BM + 4];
    __shared__ float Bs[BK][BN];
    __shared__ int   toks[BM];

    int tid = threadIdx.x;
    int r0  = blockIdx.y * BM;
    int n0  = blockIdx.x * BN;

    if (tid < BM) {
        int r = r0 + tid;
        int b = r & 63;
        int t = r >> 6;
        toks[tid] = seq[b * SEQT + t];
    }
    __syncthreads();

    int tx = tid & 15;
    int ty = tid >> 4;

    ull acc[8][2];
#pragma unroll
    for (int i = 0; i < 8; i++) { acc[i][0] = 0ull; acc[i][1] = 0ull; }

    for (int kb = 0; kb < KPAD; kb += BK) {
#pragma unroll
        for (int l = 0; l < 2; l++) {
            int fidx = tid + l * 256;
            int m    = fidx >> 2;
            int kq   = (fidx & 3) * 4;
            int k    = kb + kq;
            float4 v = make_float4(0.f, 0.f, 0.f, 0.f);
            if (k < EDIM)
                v = *(const float4*)(emb + (size_t)toks[m] * EDIM + k);
            As[kq + 0][m] = v.x;
            As[kq + 1][m] = v.y;
            As[kq + 2][m] = v.z;
            As[kq + 3][m] = v.w;
        }
        {
            int k  = tid >> 4;
            int nq = (tid & 15) * 4;
            float4 v = *(const float4*)(g_WIT + (size_t)(kb + k) * G4 + n0 + nq);
            *(float4*)&Bs[k][nq] = v;
        }
        __syncthreads();

#pragma unroll
        for (int k = 0; k < BK; k++) {
            ull b01 = *(const ull*)&Bs[k][tx * 4];
            ull b23 = *(const ull*)&Bs[k][tx * 4 + 2];
            float a0[4], a1[4];
            *(float4*)a0 = *(const float4*)&As[k][ty * 8];
            *(float4*)a1 = *(const float4*)&As[k][ty * 8 + 4];
#pragma unroll
            for (int i = 0; i < 4; i++) {
                ull aaA = pk2(a0[i], a0[i]);
                ull aaB = pk2(a1[i], a1[i]);
                acc[i][0]     = ffma2(aaA, b01, acc[i][0]);
                acc[i][1]     = ffma2(aaA, b23, acc[i][1]);
                acc[i + 4][0] = ffma2(aaB, b01, acc[i + 4][0]);
                acc[i + 4][1] = ffma2(aaB, b23, acc[i + 4][1]);
            }
        }
        __syncthreads();
    }

    int n = n0 + tx * 4;
    float4 bi = *(const float4*)(b_ih + n);
    float4 bh = *(const float4*)(b_hh + n);

#pragma unroll
    for (int i = 0; i < 8; i++) {
        int r = r0 + ty * 8 + i;
        float x, y, z, w;
        unpk2(acc[i][0], x, y);
        unpk2(acc[i][1], z, w);
        float4 o = make_float4(x + bi.x + bh.x, y + bi.y + bh.y,
                               z + bi.z + bh.z, w + bi.w + bh.w);
        *(float4*)(g_XG + (size_t)r * G4 + n) = o;
    }
}

// ---------------------------------------------------------------------------
// Persistent LSTM. 128 blocks x 256 threads, W_hh register-resident.
// GEMV software-pipelined: double-buffered half-batch h slices so ~16
// LDG.128 stay in flight under the FFMA2 stream. Split-phase global barrier:
// arrive right after h publish; DRAM out-stores + xg prefetch run between
// arrive and wait.
// ---------------------------------------------------------------------------
__device__ __forceinline__ void load_half(ull* buf, const float* p) {
#pragma unroll
    for (int m = 0; m < 8; m++)
        ldcg_u64x2(p + (m << 5), buf[2 * m], buf[2 * m + 1]);
}

__global__ void __launch_bounds__(256, 1) lstm_persistent(
    const float* __restrict__ W_hh,
    const int*   __restrict__ lengths,
    float* __restrict__ out)
{
    __shared__ float Ex[16 * 69];   // [lr][b], pitch 69

    const int tid  = threadIdx.x;
    const int bk   = blockIdx.x;
    const int lane = tid & 31;
    const int w    = tid >> 5;
    const int rg   = w & 1;
    const int bgrp = w >> 1;        // 0..3 (16 batches each)
    const int kc   = lane & 7;
    const int rp   = lane >> 3;     // 0..3

    const int lr0 = rg * 8 + rp * 2;
    const int lr1 = lr0 + 1;
    // lr = gate*4 + jj  ->  W_hh row = gate*512 + 4*bk + jj
    const int row0 = ((lr0 >> 2) << 9) + 4 * bk + (lr0 & 3);
    const int row1 = ((lr1 >> 2) << 9) + 4 * bk + (lr1 & 3);

    // --- W slice into registers: pair i=(2m,2m+1) covers k = m*32 + kc*4 ..+3
    ull W0[32], W1[32];
#pragma unroll
    for (int m = 0; m < 16; m++) {
        const float* p0 = W_hh + (size_t)row0 * HC + m * 32 + kc * 4;
        const float* p1 = W_hh + (size_t)row1 * HC + m * 32 + kc * 4;
        ulonglong2 v0 = *(const ulonglong2*)p0;
        ulonglong2 v1 = *(const ulonglong2*)p1;
        W0[2 * m] = v0.x; W0[2 * m + 1] = v0.y;
        W1[2 * m] = v1.x; W1[2 * m + 1] = v1.y;
    }

    // --- replay-safe epoch base (all blocks read before barrier 1 can flip)
    unsigned e0 = 0;
    if (tid == 0) e0 = ld_acq(&g_epoch);

    // --- init published h (parity 0) via .cg
    stcg_f(&g_H[0][bk * 256 + tid], 0.f);

    // --- pointwise identity
    const int jj   = tid & 3;
    const int b_pt = tid >> 2;
    const int j_pt = 4 * bk + jj;
    const int len_b = lengths[b_pt];
    float h_st = 0.f, c_st = 0.f;

    __syncthreads();
    if (tid == 0) { bar_arrive(e0 + 1); bar_wait(e0 + 1); }
    __syncthreads();

    // prefetch xg for t=0
    float xi, xf, xgv, xo;
    {
        const float* xg = g_XG + (size_t)b_pt * G4;
        xi  = ldcg_f(xg + j_pt);
        xf  = ldcg_f(xg + 512 + j_pt);
        xgv = ldcg_f(xg + 1024 + j_pt);
        xo  = ldcg_f(xg + 1536 + j_pt);
    }

#pragma unroll 1
    for (int t = 0; t < SEQT; t++) {
        const int p = t & 1;
        const float* hbase = g_H[p] + (bgrp << 13) + (kc << 2);

        // ---- pipelined recurrence GEMV ----
        ull hxA[16], hxB[16];
        load_half(hxA, hbase);                     // bb=0, half0
#pragma unroll 2
        for (int bb = 0; bb < 16; bb++) {
            const float* hb = hbase + (bb << 9);
            load_half(hxB, hb + 256);              // this batch, half1
            ull a0 = 0ull, a1 = 0ull;
#pragma unroll
            for (int m = 0; m < 16; m++) {
                a0 = ffma2(W0[m], hxA[m], a0);
                a1 = ffma2(W1[m], hxA[m], a1);
            }
            if (bb < 15) load_half(hxA, hb + 512); // next batch, half0
#pragma unroll
            for (int m = 0; m < 16; m++) {
                a0 = ffma2(W0[16 + m], hxB[m], a0);
                a1 = ffma2(W1[16 + m], hxB[m], a1);
            }
            float s0 = hsum2(a0);
            float s1 = hsum2(a1);
            s0 += __shfl_xor_sync(0xffffffffu, s0, 1);
            s0 += __shfl_xor_sync(0xffffffffu, s0, 2);
            s0 += __shfl_xor_sync(0xffffffffu, s0, 4);
            s1 += __shfl_xor_sync(0xffffffffu, s1, 1);
            s1 += __shfl_xor_sync(0xffffffffu, s1, 2);
            s1 += __shfl_xor_sync(0xffffffffu, s1, 4);
            if (kc == 0) {
                int b = bgrp * 16 + bb;
                Ex[lr0 * 69 + b] = s0;
                Ex[lr1 * 69 + b] = s1;
            }
        }
        __syncthreads();

        // ---- pointwise LSTM update ----
        float pi = xi  + Ex[(0  + jj) * 69 + b_pt];
        float pf = xf  + Ex[(4  + jj) * 69 + b_pt];
        float pg = xgv + Ex[(8  + jj) * 69 + b_pt];
        float po = xo  + Ex[(12 + jj) * 69 + b_pt];

        float gi = 1.f / (1.f + expf(-pi));
        float gf = 1.f / (1.f + expf(-pf));
        float gg = tanhf(pg);
        float go = 1.f / (1.f + expf(-po));

        float cn = gf * c_st + gi * gg;
        float hn = go * tanhf(cn);

        bool msk = (t < len_b);
        if (msk) { c_st = cn; h_st = hn; }
        stcg_f(&g_H[p ^ 1][(b_pt << 9) + j_pt], h_st);

        __syncthreads();                     // all h stores done
        if (tid == 0) bar_arrive(e0 + t + 2);

        // DRAM out-stores + next-step xg prefetch hide under the spin
        size_t o = (size_t)b_pt * (SEQT * HC) + (size_t)t * HC + j_pt;
        out[o]                = msk ? hn : 0.f;
        out[OUT_CELL_OFF + o] = msk ? cn : 0.f;

        if (t + 1 < SEQT) {
            const float* xg = g_XG + (size_t)(t + 1) * (BATCH * G4)
                                   + (size_t)b_pt * G4;
            xi  = ldcg_f(xg + j_pt);
            xf  = ldcg_f(xg + 512 + j_pt);
            xgv = ldcg_f(xg + 1024 + j_pt);
            xo  = ldcg_f(xg + 1536 + j_pt);
        }

        if (tid == 0) bar_wait(e0 + t + 2);
        __syncthreads();
    }

    // ---- final h, c ----
    {
        size_t e = (size_t)b_pt * HC + j_pt;
        out[OUT_H_OFF + e] = h_st;
        out[OUT_C_OFF + e] = c_st;
    }
}

// ---------------------------------------------------------------------------
extern "C" void kernel_launch(void* const* d_in, const int* in_sizes, int n_in,
                              void* d_out, int out_size) {
    const int*   seq     = (const int*)d_in[0];
    const int*   lengths = (const int*)d_in[1];
    const float* emb     = (const float*)d_in[2];
    const float* W_ih    = (const float*)d_in[3];
    const float* W_hh    = (const float*)d_in[4];
    const float* b_ih    = (const float*)d_in[5];
    const float* b_hh    = (const float*)d_in[6];
    float* out = (float*)d_out;

    transpose_wih<<<dim3(64, 10), dim3(32, 8)>>>(W_ih);
    embed_gemm<<<dim3(32, 256), 256>>>(seq, emb, b_ih, b_hh);
    lstm_persistent<<<NBLK, 256>>>(W_hh, lengths, out);
}

// round 5
// speedup vs baseline: 4.6565x; 1.1202x over previous
#include <cuda_runtime.h>
#include <math.h>
#include <stdint.h>

#define BATCH 64
#define SEQT  512
#define EDIM  300
#define KPAD  304
#define HC    512
#define G4    2048   // 4*HC
#define NBLK  128

typedef unsigned long long ull;

// ---- scratch (device globals: allocation-free rule) ----
__device__ float g_XG[(size_t)SEQT * BATCH * G4];   // [t][b][g]
__device__ float g_WIT[KPAD * G4];                  // [k][g]
__device__ float g_H[2][BATCH * HC];                // double-buffered hidden (L2-scope)
__device__ unsigned int g_count;                    // barrier counter (self-resetting)
__device__ unsigned int g_epoch;                    // barrier epoch (monotonic)

#define OUT_CELL_OFF  ((size_t)BATCH * SEQT * HC)
#define OUT_H_OFF     (2 * OUT_CELL_OFF)
#define OUT_C_OFF     (OUT_H_OFF + (size_t)BATCH * HC)

// ---------------- packed fp32x2 helpers (sm_100+) ----------------
__device__ __forceinline__ ull ffma2(ull a, ull b, ull c) {
    ull d;
    asm("fma.rn.f32x2 %0, %1, %2, %3;" : "=l"(d) : "l"(a), "l"(b), "l"(c));
    return d;
}
__device__ __forceinline__ ull pk2(float x, float y) {
    ull r;
    asm("mov.b64 %0, {%1, %2};" : "=l"(r)
        : "r"(__float_as_uint(x)), "r"(__float_as_uint(y)));
    return r;
}
__device__ __forceinline__ float hsum2(ull v) {
    unsigned a, b;
    asm("mov.b64 {%0, %1}, %2;" : "=r"(a), "=r"(b) : "l"(v));
    return __uint_as_float(a) + __uint_as_float(b);
}
__device__ __forceinline__ void unpk2(ull v, float& x, float& y) {
    unsigned a, b;
    asm("mov.b64 {%0, %1}, %2;" : "=r"(a), "=r"(b) : "l"(v));
    x = __uint_as_float(a); y = __uint_as_float(b);
}

// ---------------- L2-scope (.cg) accessors ----------------
__device__ __forceinline__ float ldcg_f(const float* p) {
    float v;
    asm volatile("ld.global.cg.f32 %0, [%1];" : "=f"(v) : "l"(p));
    return v;
}
__device__ __forceinline__ void stcg_f(float* p, float v) {
    asm volatile("st.global.cg.f32 [%0], %1;" :: "l"(p), "f"(v));
}

// ---------------- cp.async (L2 -> SMEM, bypass L1) ----------------
__device__ __forceinline__ void cp16(unsigned smem_dst, const float* gsrc) {
    asm volatile("cp.async.cg.shared.global [%0], [%1], 16;"
                 :: "r"(smem_dst), "l"(gsrc));
}
#define CP_COMMIT()  asm volatile("cp.async.commit_group;" ::: "memory")
#define CP_WAIT(N)   asm volatile("cp.async.wait_group %0;" :: "n"(N) : "memory")

// ---------------- scoped-atomic barrier primitives ----------------
__device__ __forceinline__ unsigned ld_acq(const unsigned* p) {
    unsigned v;
    asm volatile("ld.acquire.gpu.global.u32 %0, [%1];" : "=r"(v) : "l"(p) : "memory");
    return v;
}
__device__ __forceinline__ void st_rel(unsigned* p, unsigned v) {
    asm volatile("st.release.gpu.global.u32 [%0], %1;" :: "l"(p), "r"(v) : "memory");
}
__device__ __forceinline__ unsigned atom_add_rel(unsigned* p, unsigned v) {
    unsigned old;
    asm volatile("atom.release.gpu.global.add.u32 %0, [%1], %2;"
                 : "=r"(old) : "l"(p), "r"(v) : "memory");
    return old;
}
__device__ __forceinline__ void bar_arrive(unsigned target) {
    if (atom_add_rel(&g_count, 1) == NBLK - 1) {
        g_count = 0;
        st_rel(&g_epoch, target);
    }
}
__device__ __forceinline__ void bar_wait(unsigned target) {
    while (ld_acq(&g_epoch) != target) { }
}

// ---------------------------------------------------------------------------
// W_ih [2048,300] -> g_WIT [304,2048]
// ---------------------------------------------------------------------------
__global__ void transpose_wih(const float* __restrict__ W_ih) {
    __shared__ float tile[32][33];
    int n0 = blockIdx.x * 32;
    int k0 = blockIdx.y * 32;
    int tx = threadIdx.x;
    int ty = threadIdx.y;
#pragma unroll
    for (int i = 0; i < 32; i += 8) {
        int n = n0 + ty + i;
        int k = k0 + tx;
        tile[ty + i][tx] = (k < EDIM) ? W_ih[(size_t)n * EDIM + k] : 0.f;
    }
    __syncthreads();
#pragma unroll
    for (int i = 0; i < 32; i += 8) {
        int k = k0 + ty + i;
        int n = n0 + tx;
        if (k < KPAD) g_WIT[(size_t)k * G4 + n] = tile[tx][ty + i];
    }
}

// ---------------------------------------------------------------------------
// Input GEMM: XG[r][n] = emb[tok(r)] . WIT[:,n] + b_ih[n] + b_hh[n]
// ---------------------------------------------------------------------------
#define BM 128
#define BN 64
#define BK 16

__global__ void __launch_bounds__(256) embed_gemm(
    const int* __restrict__ seq,
    const float* __restrict__ emb,
    const float* __restrict__ b_ih,
    const float* __restrict__ b_hh)
{
    __shared__ float As[BK][BM + 4];
    __shared__ float Bs[BK][BN];
    __shared__ int   toks[BM];

    int tid = threadIdx.x;
    int r0  = blockIdx.y * BM;
    int n0  = blockIdx.x * BN;

    if (tid < BM) {
        int r = r0 + tid;
        int b = r & 63;
        int t = r >> 6;
        toks[tid] = seq[b * SEQT + t];
    }
    __syncthreads();

    int tx = tid & 15;
    int ty = tid >> 4;

    ull acc[8][2];
#pragma unroll
    for (int i = 0; i < 8; i++) { acc[i][0] = 0ull; acc[i][1] = 0ull; }

    for (int kb = 0; kb < KPAD; kb += BK) {
#pragma unroll
        for (int l = 0; l < 2; l++) {
            int fidx = tid + l * 256;
            int m    = fidx >> 2;
            int kq   = (fidx & 3) * 4;
            int k    = kb + kq;
            float4 v = make_float4(0.f, 0.f, 0.f, 0.f);
            if (k < EDIM)
                v = *(const float4*)(emb + (size_t)toks[m] * EDIM + k);
            As[kq + 0][m] = v.x;
            As[kq + 1][m] = v.y;
            As[kq + 2][m] = v.z;
            As[kq + 3][m] = v.w;
        }
        {
            int k  = tid >> 4;
            int nq = (tid & 15) * 4;
            float4 v = *(const float4*)(g_WIT + (size_t)(kb + k) * G4 + n0 + nq);
            *(float4*)&Bs[k][nq] = v;
        }
        __syncthreads();

#pragma unroll
        for (int k = 0; k < BK; k++) {
            ull b01 = *(const ull*)&Bs[k][tx * 4];
            ull b23 = *(const ull*)&Bs[k][tx * 4 + 2];
            float a0[4], a1[4];
            *(float4*)a0 = *(const float4*)&As[k][ty * 8];
            *(float4*)a1 = *(const float4*)&As[k][ty * 8 + 4];
#pragma unroll
            for (int i = 0; i < 4; i++) {
                ull aaA = pk2(a0[i], a0[i]);
                ull aaB = pk2(a1[i], a1[i]);
                acc[i][0]     = ffma2(aaA, b01, acc[i][0]);
                acc[i][1]     = ffma2(aaA, b23, acc[i][1]);
                acc[i + 4][0] = ffma2(aaB, b01, acc[i + 4][0]);
                acc[i + 4][1] = ffma2(aaB, b23, acc[i + 4][1]);
            }
        }
        __syncthreads();
    }

    int n = n0 + tx * 4;
    float4 bi = *(const float4*)(b_ih + n);
    float4 bh = *(const float4*)(b_hh + n);

#pragma unroll
    for (int i = 0; i < 8; i++) {
        int r = r0 + ty * 8 + i;
        float x, y, z, w;
        unpk2(acc[i][0], x, y);
        unpk2(acc[i][1], z, w);
        float4 o = make_float4(x + bi.x + bh.x, y + bi.y + bh.y,
                               z + bi.z + bh.z, w + bi.w + bh.w);
        *(float4*)(g_XG + (size_t)r * G4 + n) = o;
    }
}

// ---------------------------------------------------------------------------
// Persistent LSTM. 128 blocks x 256 threads, W_hh register-resident.
// Per step: h staged L2->SMEM once per block via cp.async in two batch-halves
// (A = batches b%16<8, B = rest) so group B streams in under group A's FMAs.
// GEMV reads h from SMEM (broadcast LDS, conflict-free). Split-phase global
// barrier; out-stores + xg prefetch hide in the barrier shadow.
// ---------------------------------------------------------------------------
__global__ void __launch_bounds__(256, 1) lstm_persistent(
    const float* __restrict__ W_hh,
    const int*   __restrict__ lengths,
    float* __restrict__ out)
{
    extern __shared__ float dynsm[];
    float* sm_h = dynsm;                 // [64][512]
    float* Ex   = dynsm + BATCH * HC;    // [16][69]

    const int tid  = threadIdx.x;
    const int bk   = blockIdx.x;
    const int lane = tid & 31;
    const int w    = tid >> 5;
    const int rg   = w & 1;
    const int bgrp = w >> 1;        // 0..3 (16 batches each)
    const int kc   = lane & 7;
    const int rp   = lane >> 3;     // 0..3

    const int lr0 = rg * 8 + rp * 2;
    const int lr1 = lr0 + 1;
    // lr = gate*4 + jj  ->  W_hh row = gate*512 + 4*bk + jj
    const int row0 = ((lr0 >> 2) << 9) + 4 * bk + (lr0 & 3);
    const int row1 = ((lr1 >> 2) << 9) + 4 * bk + (lr1 & 3);

    // --- W slice into registers: pair (2m,2m+1) covers k = m*32 + kc*4 ..+3
    ull W0[32], W1[32];
#pragma unroll
    for (int m = 0; m < 16; m++) {
        const float* p0 = W_hh + (size_t)row0 * HC + m * 32 + kc * 4;
        const float* p1 = W_hh + (size_t)row1 * HC + m * 32 + kc * 4;
        ulonglong2 v0 = *(const ulonglong2*)p0;
        ulonglong2 v1 = *(const ulonglong2*)p1;
        W0[2 * m] = v0.x; W0[2 * m + 1] = v0.y;
        W1[2 * m] = v1.x; W1[2 * m + 1] = v1.y;
    }

    const unsigned sm_h_u32 = (unsigned)__cvta_generic_to_shared(sm_h);

    // --- replay-safe epoch base
    unsigned e0 = 0;
    if (tid == 0) e0 = ld_acq(&g_epoch);

    // --- init published h (parity 0) via .cg
    stcg_f(&g_H[0][bk * 256 + tid], 0.f);

    // --- pointwise identity
    const int jj   = tid & 3;
    const int b_pt = tid >> 2;
    const int j_pt = 4 * bk + jj;
    const int len_b = lengths[b_pt];
    float h_st = 0.f, c_st = 0.f;

    __syncthreads();
    if (tid == 0) { bar_arrive(e0 + 1); bar_wait(e0 + 1); }
    __syncthreads();

    // prefetch xg for t=0
    float xi, xf, xgv, xo;
    {
        const float* xg = g_XG + (size_t)b_pt * G4;
        xi  = ldcg_f(xg + j_pt);
        xf  = ldcg_f(xg + 512 + j_pt);
        xgv = ldcg_f(xg + 1024 + j_pt);
        xo  = ldcg_f(xg + 1536 + j_pt);
    }

#pragma unroll 1
    for (int t = 0; t < SEQT; t++) {
        const int p = t & 1;
        const float* h_in = g_H[p];

        // ---- stage h into SMEM: group A (b%16<8) then group B via cp.async
#pragma unroll
        for (int grp = 0; grp < 2; grp++) {
#pragma unroll
            for (int i = 0; i < 16; i++) {
                int lin = tid + (i << 8);            // 0..4095 16B chunks
                int r   = lin >> 7;                  // 0..31 rows in group
                int off = (lin & 127) << 2;          // float offset in row
                int b   = ((r >> 3) << 4) + grp * 8 + (r & 7);
                cp16(sm_h_u32 + (unsigned)(((b << 9) + off) << 2),
                     h_in + (b << 9) + off);
            }
            CP_COMMIT();
        }
        CP_WAIT(1);          // group A resident
        __syncthreads();

        // ---- GEMV: batches 0..7 (group A), then 8..15 (group B)
#pragma unroll 1
        for (int bb = 0; bb < 16; bb++) {
            if (bb == 8) {
                CP_WAIT(0);  // group B resident
                __syncthreads();
            }
            const int b = bgrp * 16 + bb;
            const float* hb = sm_h + (b << 9) + (kc << 2);

            ull a0 = 0ull, a1 = 0ull;
#pragma unroll
            for (int m = 0; m < 16; m++) {
                ulonglong2 hv = *(const ulonglong2*)(hb + (m << 5));
                a0 = ffma2(W0[2 * m],     hv.x, a0);
                a0 = ffma2(W0[2 * m + 1], hv.y, a0);
                a1 = ffma2(W1[2 * m],     hv.x, a1);
                a1 = ffma2(W1[2 * m + 1], hv.y, a1);
            }
            float s0 = hsum2(a0);
            float s1 = hsum2(a1);
            s0 += __shfl_xor_sync(0xffffffffu, s0, 1);
            s0 += __shfl_xor_sync(0xffffffffu, s0, 2);
            s0 += __shfl_xor_sync(0xffffffffu, s0, 4);
            s1 += __shfl_xor_sync(0xffffffffu, s1, 1);
            s1 += __shfl_xor_sync(0xffffffffu, s1, 2);
            s1 += __shfl_xor_sync(0xffffffffu, s1, 4);
            if (kc == 0) {
                Ex[lr0 * 69 + b] = s0;
                Ex[lr1 * 69 + b] = s1;
            }
        }
        __syncthreads();

        // ---- pointwise LSTM update ----
        float pi = xi  + Ex[(0  + jj) * 69 + b_pt];
        float pf = xf  + Ex[(4  + jj) * 69 + b_pt];
        float pg = xgv + Ex[(8  + jj) * 69 + b_pt];
        float po = xo  + Ex[(12 + jj) * 69 + b_pt];

        float gi = 1.f / (1.f + expf(-pi));
        float gf = 1.f / (1.f + expf(-pf));
        float gg = tanhf(pg);
        float go = 1.f / (1.f + expf(-po));

        float cn = gf * c_st + gi * gg;
        float hn = go * tanhf(cn);

        bool msk = (t < len_b);
        if (msk) { c_st = cn; h_st = hn; }
        stcg_f(&g_H[p ^ 1][(b_pt << 9) + j_pt], h_st);

        __syncthreads();                     // all h stores done
        if (tid == 0) bar_arrive(e0 + t + 2);

        // DRAM out-stores + next-step xg prefetch hide under the spin
        size_t o = (size_t)b_pt * (SEQT * HC) + (size_t)t * HC + j_pt;
        out[o]                = msk ? hn : 0.f;
        out[OUT_CELL_OFF + o] = msk ? cn : 0.f;

        if (t + 1 < SEQT) {
            const float* xg = g_XG + (size_t)(t + 1) * (BATCH * G4)
                                   + (size_t)b_pt * G4;
            xi  = ldcg_f(xg + j_pt);
            xf  = ldcg_f(xg + 512 + j_pt);
            xgv = ldcg_f(xg + 1024 + j_pt);
            xo  = ldcg_f(xg + 1536 + j_pt);
        }

        if (tid == 0) bar_wait(e0 + t + 2);
        __syncthreads();
    }

    // ---- final h, c ----
    {
        size_t e = (size_t)b_pt * HC + j_pt;
        out[OUT_H_OFF + e] = h_st;
        out[OUT_C_OFF + e] = c_st;
    }
}

// ---------------------------------------------------------------------------
extern "C" void kernel_launch(void* const* d_in, const int* in_sizes, int n_in,
                              void* d_out, int out_size) {
    const int*   seq     = (const int*)d_in[0];
    const int*   lengths = (const int*)d_in[1];
    const float* emb     = (const float*)d_in[2];
    const float* W_ih    = (const float*)d_in[3];
    const float* W_hh    = (const float*)d_in[4];
    const float* b_ih    = (const float*)d_in[5];
    const float* b_hh    = (const float*)d_in[6];
    float* out = (float*)d_out;

    const int LSTM_SMEM = (BATCH * HC + 16 * 69) * 4;   // 135,488 B
    cudaFuncSetAttribute(lstm_persistent,
                         cudaFuncAttributeMaxDynamicSharedMemorySize, LSTM_SMEM);

    transpose_wih<<<dim3(64, 10), dim3(32, 8)>>>(W_ih);
    embed_gemm<<<dim3(32, 256), 256>>>(seq, emb, b_ih, b_hh);
    lstm_persistent<<<NBLK, 256, LSTM_SMEM>>>(W_hh, lengths, out);
}

// round 6
// speedup vs baseline: 4.8545x; 1.0425x over previous
#include <cuda_runtime.h>
#include <math.h>
#include <stdint.h>

#define BATCH 64
#define SEQT  512
#define EDIM  300
#define KPAD  304
#define HC    512
#define G4    2048   // 4*HC
#define NBLK  128
#define NGRP  32     // blocks per bq barrier group

typedef unsigned long long ull;

// ---- scratch (device globals: allocation-free rule) ----
__device__ float g_XG[(size_t)SEQT * BATCH * G4];   // [t][b][g]
__device__ float g_WIT[KPAD * G4];                  // [k][g]
__device__ float g_H[2][BATCH * HC];                // double-buffered hidden (L2-scope)
__device__ unsigned int g_count4[4];                // per-bq barrier counters
__device__ unsigned int g_epoch4[4];                // per-bq barrier epochs

#define OUT_CELL_OFF  ((size_t)BATCH * SEQT * HC)
#define OUT_H_OFF     (2 * OUT_CELL_OFF)
#define OUT_C_OFF     (OUT_H_OFF + (size_t)BATCH * HC)

// ---------------- packed fp32x2 helpers (sm_100+) ----------------
__device__ __forceinline__ ull ffma2(ull a, ull b, ull c) {
    ull d;
    asm("fma.rn.f32x2 %0, %1, %2, %3;" : "=l"(d) : "l"(a), "l"(b), "l"(c));
    return d;
}
__device__ __forceinline__ ull pk2(float x, float y) {
    ull r;
    asm("mov.b64 %0, {%1, %2};" : "=l"(r)
        : "r"(__float_as_uint(x)), "r"(__float_as_uint(y)));
    return r;
}
__device__ __forceinline__ float hsum2(ull v) {
    unsigned a, b;
    asm("mov.b64 {%0, %1}, %2;" : "=r"(a), "=r"(b) : "l"(v));
    return __uint_as_float(a) + __uint_as_float(b);
}
__device__ __forceinline__ void unpk2(ull v, float& x, float& y) {
    unsigned a, b;
    asm("mov.b64 {%0, %1}, %2;" : "=r"(a), "=r"(b) : "l"(v));
    x = __uint_as_float(a); y = __uint_as_float(b);
}

// ---------------- L2-scope (.cg) accessors ----------------
__device__ __forceinline__ float ldcg_f(const float* p) {
    float v;
    asm volatile("ld.global.cg.f32 %0, [%1];" : "=f"(v) : "l"(p));
    return v;
}
__device__ __forceinline__ void stcg_f(float* p, float v) {
    asm volatile("st.global.cg.f32 [%0], %1;" :: "l"(p), "f"(v));
}

// ---------------- cp.async (L2 -> SMEM, bypass L1) ----------------
__device__ __forceinline__ void cp16(unsigned smem_dst, const float* gsrc) {
    asm volatile("cp.async.cg.shared.global [%0], [%1], 16;"
                 :: "r"(smem_dst), "l"(gsrc));
}
#define CP_COMMIT()  asm volatile("cp.async.commit_group;" ::: "memory")
#define CP_WAIT(N)   asm volatile("cp.async.wait_group %0;" :: "n"(N) : "memory")

// ---------------- scoped-atomic barrier primitives ----------------
__device__ __forceinline__ unsigned ld_acq(const unsigned* p) {
    unsigned v;
    asm volatile("ld.acquire.gpu.global.u32 %0, [%1];" : "=r"(v) : "l"(p) : "memory");
    return v;
}
__device__ __forceinline__ void st_rel(unsigned* p, unsigned v) {
    asm volatile("st.release.gpu.global.u32 [%0], %1;" :: "l"(p), "r"(v) : "memory");
}
__device__ __forceinline__ unsigned atom_add_rel(unsigned* p, unsigned v) {
    unsigned old;
    asm volatile("atom.release.gpu.global.add.u32 %0, [%1], %2;"
                 : "=r"(old) : "l"(p), "r"(v) : "memory");
    return old;
}
__device__ __forceinline__ void bar_arrive(int bq, unsigned target) {
    if (atom_add_rel(&g_count4[bq], 1) == NGRP - 1) {
        g_count4[bq] = 0;
        st_rel(&g_epoch4[bq], target);
    }
}
__device__ __forceinline__ void bar_wait(int bq, unsigned target) {
    while (ld_acq(&g_epoch4[bq]) != target) { }
}

// ---------------------------------------------------------------------------
// W_ih [2048,300] -> g_WIT [304,2048]
// ---------------------------------------------------------------------------
__global__ void transpose_wih(const float* __restrict__ W_ih) {
    __shared__ float tile[32][33];
    int n0 = blockIdx.x * 32;
    int k0 = blockIdx.y * 32;
    int tx = threadIdx.x;
    int ty = threadIdx.y;
#pragma unroll
    for (int i = 0; i < 32; i += 8) {
        int n = n0 + ty + i;
        int k = k0 + tx;
        tile[ty + i][tx] = (k < EDIM) ? W_ih[(size_t)n * EDIM + k] : 0.f;
    }
    __syncthreads();
#pragma unroll
    for (int i = 0; i < 32; i += 8) {
        int k = k0 + ty + i;
        int n = n0 + tx;
        if (k < KPAD) g_WIT[(size_t)k * G4 + n] = tile[tx][ty + i];
    }
}

// ---------------------------------------------------------------------------
// Input GEMM: XG[r][n] = emb[tok(r)] . WIT[:,n] + b_ih[n] + b_hh[n]
// ---------------------------------------------------------------------------
#define BM 128
#define BN 64
#define BK 16

__global__ void __launch_bounds__(256) embed_gemm(
    const int* __restrict__ seq,
    const float* __restrict__ emb,
    const float* __restrict__ b_ih,
    const float* __restrict__ b_hh)
{
    __shared__ float As[BK][BM + 4];
    __shared__ float Bs[BK][BN];
    __shared__ int   toks[BM];

    int tid = threadIdx.x;
    int r0  = blockIdx.y * BM;
    int n0  = blockIdx.x * BN;

    if (tid < BM) {
        int r = r0 + tid;
        int b = r & 63;
        int t = r >> 6;
        toks[tid] = seq[b * SEQT + t];
    }
    __syncthreads();

    int tx = tid & 15;
    int ty = tid >> 4;

    ull acc[8][2];
#pragma unroll
    for (int i = 0; i < 8; i++) { acc[i][0] = 0ull; acc[i][1] = 0ull; }

    for (int kb = 0; kb < KPAD; kb += BK) {
#pragma unroll
        for (int l = 0; l < 2; l++) {
            int fidx = tid + l * 256;
            int m    = fidx >> 2;
            int kq   = (fidx & 3) * 4;
            int k    = kb + kq;
            float4 v = make_float4(0.f, 0.f, 0.f, 0.f);
            if (k < EDIM)
                v = *(const float4*)(emb + (size_t)toks[m] * EDIM + k);
            As[kq + 0][m] = v.x;
            As[kq + 1][m] = v.y;
            As[kq + 2][m] = v.z;
            As[kq + 3][m] = v.w;
        }
        {
            int k  = tid >> 4;
            int nq = (tid & 15) * 4;
            float4 v = *(const float4*)(g_WIT + (size_t)(kb + k) * G4 + n0 + nq);
            *(float4*)&Bs[k][nq] = v;
        }
        __syncthreads();

#pragma unroll
        for (int k = 0; k < BK; k++) {
            ull b01 = *(const ull*)&Bs[k][tx * 4];
            ull b23 = *(const ull*)&Bs[k][tx * 4 + 2];
            float a0[4], a1[4];
            *(float4*)a0 = *(const float4*)&As[k][ty * 8];
            *(float4*)a1 = *(const float4*)&As[k][ty * 8 + 4];
#pragma unroll
            for (int i = 0; i < 4; i++) {
                ull aaA = pk2(a0[i], a0[i]);
                ull aaB = pk2(a1[i], a1[i]);
                acc[i][0]     = ffma2(aaA, b01, acc[i][0]);
                acc[i][1]     = ffma2(aaA, b23, acc[i][1]);
                acc[i + 4][0] = ffma2(aaB, b01, acc[i + 4][0]);
                acc[i + 4][1] = ffma2(aaB, b23, acc[i + 4][1]);
            }
        }
        __syncthreads();
    }

    int n = n0 + tx * 4;
    float4 bi = *(const float4*)(b_ih + n);
    float4 bh = *(const float4*)(b_hh + n);

#pragma unroll
    for (int i = 0; i < 8; i++) {
        int r = r0 + ty * 8 + i;
        float x, y, z, w;
        unpk2(acc[i][0], x, y);
        unpk2(acc[i][1], z, w);
        float4 o = make_float4(x + bi.x + bh.x, y + bi.y + bh.y,
                               z + bi.z + bh.z, w + bi.w + bh.w);
        *(float4*)(g_XG + (size_t)r * G4 + n) = o;
    }
}

// ---------------------------------------------------------------------------
// Persistent LSTM. 128 blocks = (jg 0..31) x (bq 0..3). Block owns 16 j-cols
// (all 4 gates = 64 W rows, register-resident) x 16 batches. Per step it
// stages only its batch quarter's h (32KB) via cp.async (two halves, second
// hidden under first half's FMAs). Sync is a per-bq 32-block barrier.
// ---------------------------------------------------------------------------
__global__ void __launch_bounds__(256, 1) lstm_persistent(
    const float* __restrict__ W_hh,
    const int*   __restrict__ lengths,
    float* __restrict__ out)
{
    __shared__ float sm_h[16 * HC];    // 32 KB: this bq's h
    __shared__ float Ex[64 * 17];      // [lr][bl]

    const int tid  = threadIdx.x;
    const int bk   = blockIdx.x;
    const int jg   = bk >> 2;          // 0..31
    const int bq   = bk & 3;           // 0..3
    const int lane = tid & 31;
    const int w    = tid >> 5;         // 0..7
    const int rp   = lane >> 3;        // 0..3
    const int kc   = lane & 7;         // 0..7

    // local rows lr = gate*16 + jl ; warp w owns lr in [8w, 8w+8)
    const int lr0 = w * 8 + rp * 2;
    const int lr1 = lr0 + 1;
    const int row0 = ((lr0 >> 4) << 9) + jg * 16 + (lr0 & 15);
    const int row1 = ((lr1 >> 4) << 9) + jg * 16 + (lr1 & 15);

    // --- W slice into registers: pair (2m,2m+1) covers k = m*32 + kc*4 ..+3
    ull W0[32], W1[32];
#pragma unroll
    for (int m = 0; m < 16; m++) {
        const float* p0 = W_hh + (size_t)row0 * HC + m * 32 + kc * 4;
        const float* p1 = W_hh + (size_t)row1 * HC + m * 32 + kc * 4;
        ulonglong2 v0 = *(const ulonglong2*)p0;
        ulonglong2 v1 = *(const ulonglong2*)p1;
        W0[2 * m] = v0.x; W0[2 * m + 1] = v0.y;
        W1[2 * m] = v1.x; W1[2 * m + 1] = v1.y;
    }

    const unsigned sm_h_u32 = (unsigned)__cvta_generic_to_shared(sm_h);

    // --- replay-safe epoch base (per-bq, read before first arrive)
    unsigned e0 = 0;
    if (tid == 0) e0 = ld_acq(&g_epoch4[bq]);

    // --- pointwise identity: thread -> (bl, jl)
    const int jl   = tid & 15;
    const int bl   = tid >> 4;          // 0..15
    const int b_pt = bq * 16 + bl;
    const int j_pt = jg * 16 + jl;
    const int len_b = lengths[b_pt];
    float h_st = 0.f, c_st = 0.f;

    // --- init published h (parity 0): this block's (b,j) elements
    stcg_f(&g_H[0][(b_pt << 9) + j_pt], 0.f);

    __syncthreads();
    if (tid == 0) { bar_arrive(bq, e0 + 1); bar_wait(bq, e0 + 1); }
    __syncthreads();

    // prefetch xg for t=0
    float xi, xf, xgv, xo;
    {
        const float* xg = g_XG + (size_t)b_pt * G4;
        xi  = ldcg_f(xg + j_pt);
        xf  = ldcg_f(xg + 512 + j_pt);
        xgv = ldcg_f(xg + 1024 + j_pt);
        xo  = ldcg_f(xg + 1536 + j_pt);
    }

#pragma unroll 1
    for (int t = 0; t < SEQT; t++) {
        const int p = t & 1;
        const float* h_in = g_H[p] + ((bq * 16) << 9);

        // ---- stage this bq's h (16 rows x 512) in two 8-batch halves ----
#pragma unroll
        for (int grp = 0; grp < 2; grp++) {
#pragma unroll
            for (int i = 0; i < 4; i++) {
                int lin = tid + (i << 8);          // 0..1023 16B chunks
                int r   = lin >> 7;                // 0..7 row in half
                int off = (lin & 127) << 2;        // float offset
                int b   = grp * 8 + r;
                cp16(sm_h_u32 + (unsigned)((((b << 9) + off) << 2)),
                     h_in + (b << 9) + off);
            }
            CP_COMMIT();
        }
        CP_WAIT(1);            // first half resident
        __syncthreads();

        // ---- GEMV: batches 0..7, then 8..15 once second half lands ----
#pragma unroll 1
        for (int bb = 0; bb < 16; bb++) {
            if (bb == 8) {
                CP_WAIT(0);
                __syncthreads();
            }
            const float* hb = sm_h + (bb << 9) + (kc << 2);

            ull a0 = 0ull, a1 = 0ull;
#pragma unroll
            for (int m = 0; m < 16; m++) {
                ulonglong2 hv = *(const ulonglong2*)(hb + (m << 5));
                a0 = ffma2(W0[2 * m],     hv.x, a0);
                a0 = ffma2(W0[2 * m + 1], hv.y, a0);
                a1 = ffma2(W1[2 * m],     hv.x, a1);
                a1 = ffma2(W1[2 * m + 1], hv.y, a1);
            }
            float s0 = hsum2(a0);
            float s1 = hsum2(a1);
            s0 += __shfl_xor_sync(0xffffffffu, s0, 1);
            s0 += __shfl_xor_sync(0xffffffffu, s0, 2);
            s0 += __shfl_xor_sync(0xffffffffu, s0, 4);
            s1 += __shfl_xor_sync(0xffffffffu, s1, 1);
            s1 += __shfl_xor_sync(0xffffffffu, s1, 2);
            s1 += __shfl_xor_sync(0xffffffffu, s1, 4);
            if (kc == 0) {
                Ex[lr0 * 17 + bb] = s0;
                Ex[lr1 * 17 + bb] = s1;
            }
        }
        __syncthreads();

        // ---- pointwise LSTM update ----
        float pi = xi  + Ex[(0  + jl) * 17 + bl];
        float pf = xf  + Ex[(16 + jl) * 17 + bl];
        float pg = xgv + Ex[(32 + jl) * 17 + bl];
        float po = xo  + Ex[(48 + jl) * 17 + bl];

        float gi = 1.f / (1.f + expf(-pi));
        float gf = 1.f / (1.f + expf(-pf));
        float gg = tanhf(pg);
        float go = 1.f / (1.f + expf(-po));

        float cn = gf * c_st + gi * gg;
        float hn = go * tanhf(cn);

        bool msk = (t < len_b);
        if (msk) { c_st = cn; h_st = hn; }
        stcg_f(&g_H[p ^ 1][(b_pt << 9) + j_pt], h_st);

        __syncthreads();                 // all h stores issued
        if (tid == 0) bar_arrive(bq, e0 + t + 2);

        // DRAM out-stores + next-step xg prefetch hide under the spin
        size_t o = (size_t)b_pt * (SEQT * HC) + (size_t)t * HC + j_pt;
        out[o]                = msk ? hn : 0.f;
        out[OUT_CELL_OFF + o] = msk ? cn : 0.f;

        if (t + 1 < SEQT) {
            const float* xg = g_XG + (size_t)(t + 1) * (BATCH * G4)
                                   + (size_t)b_pt * G4;
            xi  = ldcg_f(xg + j_pt);
            xf  = ldcg_f(xg + 512 + j_pt);
            xgv = ldcg_f(xg + 1024 + j_pt);
            xo  = ldcg_f(xg + 1536 + j_pt);
        }

        if (tid == 0) bar_wait(bq, e0 + t + 2);
        __syncthreads();
    }

    // ---- final h, c ----
    {
        size_t e = (size_t)b_pt * HC + j_pt;
        out[OUT_H_OFF + e] = h_st;
        out[OUT_C_OFF + e] = c_st;
    }
}

// ---------------------------------------------------------------------------
extern "C" void kernel_launch(void* const* d_in, const int* in_sizes, int n_in,
                              void* d_out, int out_size) {
    const int*   seq     = (const int*)d_in[0];
    const int*   lengths = (const int*)d_in[1];
    const float* emb     = (const float*)d_in[2];
    const float* W_ih    = (const float*)d_in[3];
    const float* W_hh    = (const float*)d_in[4];
    const float* b_ih    = (const float*)d_in[5];
    const float* b_hh    = (const float*)d_in[6];
    float* out = (float*)d_out;

    transpose_wih<<<dim3(64, 10), dim3(32, 8)>>>(W_ih);
    embed_gemm<<<dim3(32, 256), 256>>>(seq, emb, b_ih, b_hh);
    lstm_persistent<<<NBLK, 256>>>(W_hh, lengths, out);
}

// round 7
// speedup vs baseline: 5.0952x; 1.0496x over previous
#include <cuda_runtime.h>
#include <math.h>
#include <stdint.h>

#define BATCH 64
#define SEQT  512
#define EDIM  300
#define KPAD  304
#define HC    512
#define G4    2048   // 4*HC
#define NBLK  128
#define NGRP  32     // blocks per bq barrier group

typedef unsigned long long ull;

// ---- scratch (device globals: allocation-free rule) ----
__device__ float g_XG[(size_t)SEQT * BATCH * G4];   // [t][b][g]
__device__ float g_WIT[KPAD * G4];                  // [k][g]
__device__ float g_H[2][BATCH * HC];                // double-buffered hidden (L2-scope)
__device__ unsigned int g_count4[4];                // per-bq barrier counters
__device__ unsigned int g_epoch4[4];                // per-bq barrier epochs

#define OUT_CELL_OFF  ((size_t)BATCH * SEQT * HC)
#define OUT_H_OFF     (2 * OUT_CELL_OFF)
#define OUT_C_OFF     (OUT_H_OFF + (size_t)BATCH * HC)

// ---------------- packed fp32x2 helpers (sm_100+) ----------------
__device__ __forceinline__ ull ffma2(ull a, ull b, ull c) {
    ull d;
    asm("fma.rn.f32x2 %0, %1, %2, %3;" : "=l"(d) : "l"(a), "l"(b), "l"(c));
    return d;
}
__device__ __forceinline__ ull pk2(float x, float y) {
    ull r;
    asm("mov.b64 %0, {%1, %2};" : "=l"(r)
        : "r"(__float_as_uint(x)), "r"(__float_as_uint(y)));
    return r;
}
__device__ __forceinline__ float hsum2(ull v) {
    unsigned a, b;
    asm("mov.b64 {%0, %1}, %2;" : "=r"(a), "=r"(b) : "l"(v));
    return __uint_as_float(a) + __uint_as_float(b);
}
__device__ __forceinline__ void unpk2(ull v, float& x, float& y) {
    unsigned a, b;
    asm("mov.b64 {%0, %1}, %2;" : "=r"(a), "=r"(b) : "l"(v));
    x = __uint_as_float(a); y = __uint_as_float(b);
}

// ---------------- L2-scope (.cg) accessors ----------------
__device__ __forceinline__ float ldcg_f(const float* p) {
    float v;
    asm volatile("ld.global.cg.f32 %0, [%1];" : "=f"(v) : "l"(p));
    return v;
}
__device__ __forceinline__ void stcg_f(float* p, float v) {
    asm volatile("st.global.cg.f32 [%0], %1;" :: "l"(p), "f"(v));
}

// ---------------- cp.async (L2 -> SMEM, bypass L1) ----------------
__device__ __forceinline__ void cp16(unsigned smem_dst, const float* gsrc) {
    asm volatile("cp.async.cg.shared.global [%0], [%1], 16;"
                 :: "r"(smem_dst), "l"(gsrc));
}
#define CP_COMMIT()  asm volatile("cp.async.commit_group;" ::: "memory")
#define CP_WAIT(N)   asm volatile("cp.async.wait_group %0;" :: "n"(N) : "memory")

// ---------------- scoped-atomic barrier primitives ----------------
__device__ __forceinline__ unsigned ld_acq(const unsigned* p) {
    unsigned v;
    asm volatile("ld.acquire.gpu.global.u32 %0, [%1];" : "=r"(v) : "l"(p) : "memory");
    return v;
}
__device__ __forceinline__ void st_rel(unsigned* p, unsigned v) {
    asm volatile("st.release.gpu.global.u32 [%0], %1;" :: "l"(p), "r"(v) : "memory");
}
__device__ __forceinline__ unsigned atom_add_rel(unsigned* p, unsigned v) {
    unsigned old;
    asm volatile("atom.release.gpu.global.add.u32 %0, [%1], %2;"
                 : "=r"(old) : "l"(p), "r"(v) : "memory");
    return old;
}
__device__ __forceinline__ void bar_arrive(int bq, unsigned target) {
    if (atom_add_rel(&g_count4[bq], 1) == NGRP - 1) {
        g_count4[bq] = 0;
        st_rel(&g_epoch4[bq], target);
    }
}
__device__ __forceinline__ void bar_wait(int bq, unsigned target) {
    while (ld_acq(&g_epoch4[bq]) != target) { }
}

// ---------------------------------------------------------------------------
// W_ih [2048,300] -> g_WIT [304,2048]
// ---------------------------------------------------------------------------
__global__ void transpose_wih(const float* __restrict__ W_ih) {
    __shared__ float tile[32][33];
    int n0 = blockIdx.x * 32;
    int k0 = blockIdx.y * 32;
    int tx = threadIdx.x;
    int ty = threadIdx.y;
#pragma unroll
    for (int i = 0; i < 32; i += 8) {
        int n = n0 + ty + i;
        int k = k0 + tx;
        tile[ty + i][tx] = (k < EDIM) ? W_ih[(size_t)n * EDIM + k] : 0.f;
    }
    __syncthreads();
#pragma unroll
    for (int i = 0; i < 32; i += 8) {
        int k = k0 + ty + i;
        int n = n0 + tx;
        if (k < KPAD) g_WIT[(size_t)k * G4 + n] = tile[tx][ty + i];
    }
}

// ---------------------------------------------------------------------------
// Input GEMM: XG[r][n] = emb[tok(r)] . WIT[:,n] + b_ih[n] + b_hh[n]
// Tile 128x128x16, 256 threads, 8x8 microtile (n split {tx*4, 64+tx*4}).
// ---------------------------------------------------------------------------
#define BM 128
#define BN 128
#define BK 16

__global__ void __launch_bounds__(256, 2) embed_gemm(
    const int* __restrict__ seq,
    const float* __restrict__ emb,
    const float* __restrict__ b_ih,
    const float* __restrict__ b_hh)
{
    __shared__ float As[BK][BM + 4];
    __shared__ float Bs[BK][BN];
    __shared__ int   toks[BM];

    int tid = threadIdx.x;
    int r0  = blockIdx.y * BM;
    int n0  = blockIdx.x * BN;

    if (tid < BM) {
        int r = r0 + tid;
        int b = r & 63;
        int t = r >> 6;
        toks[tid] = seq[b * SEQT + t];
    }
    __syncthreads();

    int tx = tid & 15;   // n
    int ty = tid >> 4;   // m octet

    ull acc[8][4];
#pragma unroll
    for (int i = 0; i < 8; i++)
#pragma unroll
        for (int j = 0; j < 4; j++) acc[i][j] = 0ull;

    for (int kb = 0; kb < KPAD; kb += BK) {
        // A tile: 128 rows x 16 k (gather from embedding), stored [k][m]
#pragma unroll
        for (int l = 0; l < 2; l++) {
            int fidx = tid + l * 256;          // 0..511 float4 slots
            int m    = fidx >> 2;
            int kq   = (fidx & 3) * 4;
            int k    = kb + kq;
            float4 v = make_float4(0.f, 0.f, 0.f, 0.f);
            if (k < EDIM)
                v = *(const float4*)(emb + (size_t)toks[m] * EDIM + k);
            As[kq + 0][m] = v.x;
            As[kq + 1][m] = v.y;
            As[kq + 2][m] = v.z;
            As[kq + 3][m] = v.w;
        }
        // B tile: 16 k x 128 n from WIT (coalesced), 2 float4 per thread
#pragma unroll
        for (int l = 0; l < 2; l++) {
            int fidx = tid + l * 256;          // 0..511
            int k    = fidx >> 5;
            int nq   = (fidx & 31) * 4;
            float4 v = *(const float4*)(g_WIT + (size_t)(kb + k) * G4 + n0 + nq);
            *(float4*)&Bs[k][nq] = v;
        }
        __syncthreads();

#pragma unroll
        for (int k = 0; k < BK; k++) {
            ull b0 = *(const ull*)&Bs[k][tx * 4];
            ull b1 = *(const ull*)&Bs[k][tx * 4 + 2];
            ull b2 = *(const ull*)&Bs[k][64 + tx * 4];
            ull b3 = *(const ull*)&Bs[k][64 + tx * 4 + 2];
            float a[8];
            *(float4*)a       = *(const float4*)&As[k][ty * 8];
            *(float4*)(a + 4) = *(const float4*)&As[k][ty * 8 + 4];
#pragma unroll
            for (int i = 0; i < 8; i++) {
                ull aa = pk2(a[i], a[i]);
                acc[i][0] = ffma2(aa, b0, acc[i][0]);
                acc[i][1] = ffma2(aa, b1, acc[i][1]);
                acc[i][2] = ffma2(aa, b2, acc[i][2]);
                acc[i][3] = ffma2(aa, b3, acc[i][3]);
            }
        }
        __syncthreads();
    }

    int nA = n0 + tx * 4;
    int nB = n0 + 64 + tx * 4;
    float4 biA = *(const float4*)(b_ih + nA);
    float4 bhA = *(const float4*)(b_hh + nA);
    float4 biB = *(const float4*)(b_ih + nB);
    float4 bhB = *(const float4*)(b_hh + nB);

#pragma unroll
    for (int i = 0; i < 8; i++) {
        int r = r0 + ty * 8 + i;
        float x, y, z, w;
        unpk2(acc[i][0], x, y);
        unpk2(acc[i][1], z, w);
        float4 oA = make_float4(x + biA.x + bhA.x, y + biA.y + bhA.y,
                                z + biA.z + bhA.z, w + biA.w + bhA.w);
        unpk2(acc[i][2], x, y);
        unpk2(acc[i][3], z, w);
        float4 oB = make_float4(x + biB.x + bhB.x, y + biB.y + bhB.y,
                                z + biB.z + bhB.z, w + biB.w + bhB.w);
        *(float4*)(g_XG + (size_t)r * G4 + nA) = oA;
        *(float4*)(g_XG + (size_t)r * G4 + nB) = oB;
    }
}

// ---------------------------------------------------------------------------
// Persistent LSTM. 128 blocks = (jg 0..31) x (bq 0..3). Block owns 16 j-cols
// (64 W rows register-resident) x 16 batches. h staged via cp.async in two
// halves; per-bq 32-block split-phase barrier; per-warp acquire-poll wait.
// ---------------------------------------------------------------------------
__global__ void __launch_bounds__(256, 1) lstm_persistent(
    const float* __restrict__ W_hh,
    const int*   __restrict__ lengths,
    float* __restrict__ out)
{
    __shared__ float sm_h[16 * HC];    // 32 KB: this bq's h
    __shared__ float Ex[64 * 17];      // [lr][bl]

    const int tid  = threadIdx.x;
    const int bk   = blockIdx.x;
    const int jg   = bk >> 2;          // 0..31
    const int bq   = bk & 3;           // 0..3
    const int lane = tid & 31;
    const int w    = tid >> 5;         // 0..7
    const int rp   = lane >> 3;        // 0..3
    const int kc   = lane & 7;         // 0..7

    const int lr0 = w * 8 + rp * 2;
    const int lr1 = lr0 + 1;
    const int row0 = ((lr0 >> 4) << 9) + jg * 16 + (lr0 & 15);
    const int row1 = ((lr1 >> 4) << 9) + jg * 16 + (lr1 & 15);

    // --- W slice into registers: pair (2m,2m+1) covers k = m*32 + kc*4 ..+3
    ull W0[32], W1[32];
#pragma unroll
    for (int m = 0; m < 16; m++) {
        const float* p0 = W_hh + (size_t)row0 * HC + m * 32 + kc * 4;
        const float* p1 = W_hh + (size_t)row1 * HC + m * 32 + kc * 4;
        ulonglong2 v0 = *(const ulonglong2*)p0;
        ulonglong2 v1 = *(const ulonglong2*)p1;
        W0[2 * m] = v0.x; W0[2 * m + 1] = v0.y;
        W1[2 * m] = v1.x; W1[2 * m + 1] = v1.y;
    }

    const unsigned sm_h_u32 = (unsigned)__cvta_generic_to_shared(sm_h);

    // --- replay-safe epoch base (all threads read before any arrive)
    const unsigned e0 = ld_acq(&g_epoch4[bq]);

    // --- pointwise identity: thread -> (bl, jl)
    const int jl   = tid & 15;
    const int bl   = tid >> 4;          // 0..15
    const int b_pt = bq * 16 + bl;
    const int j_pt = jg * 16 + jl;
    const int len_b = lengths[b_pt];
    float h_st = 0.f, c_st = 0.f;

    // --- init published h (parity 0): this block's (b,j) elements
    stcg_f(&g_H[0][(b_pt << 9) + j_pt], 0.f);

    __syncthreads();
    if (tid == 0) bar_arrive(bq, e0 + 1);
    bar_wait(bq, e0 + 1);

    // prefetch xg for t=0
    float xi, xf, xgv, xo;
    {
        const float* xg = g_XG + (size_t)b_pt * G4;
        xi  = ldcg_f(xg + j_pt);
        xf  = ldcg_f(xg + 512 + j_pt);
        xgv = ldcg_f(xg + 1024 + j_pt);
        xo  = ldcg_f(xg + 1536 + j_pt);
    }

#define GEMV_BATCH(bb)                                                        \
    {                                                                         \
        const float* hb = sm_h + ((bb) << 9) + (kc << 2);                     \
        ull a0 = 0ull, a1 = 0ull;                                             \
        _Pragma("unroll")                                                     \
        for (int m = 0; m < 16; m++) {                                        \
            ulonglong2 hv = *(const ulonglong2*)(hb + (m << 5));              \
            a0 = ffma2(W0[2 * m],     hv.x, a0);                              \
            a0 = ffma2(W0[2 * m + 1], hv.y, a0);                              \
            a1 = ffma2(W1[2 * m],     hv.x, a1);                              \
            a1 = ffma2(W1[2 * m + 1], hv.y, a1);                              \
        }                                                                     \
        float s0 = hsum2(a0);                                                 \
        float s1 = hsum2(a1);                                                 \
        s0 += __shfl_xor_sync(0xffffffffu, s0, 1);                            \
        s0 += __shfl_xor_sync(0xffffffffu, s0, 2);                            \
        s0 += __shfl_xor_sync(0xffffffffu, s0, 4);                            \
        s1 += __shfl_xor_sync(0xffffffffu, s1, 1);                            \
        s1 += __shfl_xor_sync(0xffffffffu, s1, 2);                            \
        s1 += __shfl_xor_sync(0xffffffffu, s1, 4);                            \
        if (kc == 0) {                                                        \
            Ex[lr0 * 17 + (bb)] = s0;                                         \
            Ex[lr1 * 17 + (bb)] = s1;                                         \
        }                                                                     \
    }

#pragma unroll 1
    for (int t = 0; t < SEQT; t++) {
        const int p = t & 1;
        const float* h_in = g_H[p] + ((bq * 16) << 9);

        // ---- stage this bq's h (16 rows x 512) in two 8-batch halves ----
#pragma unroll
        for (int grp = 0; grp < 2; grp++) {
#pragma unroll
            for (int i = 0; i < 4; i++) {
                int lin = tid + (i << 8);          // 0..1023 16B chunks
                int r   = lin >> 7;                // 0..7 row in half
                int off = (lin & 127) << 2;        // float offset
                int b   = grp * 8 + r;
                cp16(sm_h_u32 + (unsigned)((((b << 9) + off) << 2)),
                     h_in + (b << 9) + off);
            }
            CP_COMMIT();
        }
        CP_WAIT(1);            // first half resident
        __syncthreads();

#pragma unroll 2
        for (int bb = 0; bb < 8; bb++) GEMV_BATCH(bb)

        CP_WAIT(0);            // second half resident
        __syncthreads();

#pragma unroll 2
        for (int bb = 8; bb < 16; bb++) GEMV_BATCH(bb)

        __syncthreads();       // Ex complete

        // ---- pointwise LSTM update ----
        float pi = xi  + Ex[(0  + jl) * 17 + bl];
        float pf = xf  + Ex[(16 + jl) * 17 + bl];
        float pg = xgv + Ex[(32 + jl) * 17 + bl];
        float po = xo  + Ex[(48 + jl) * 17 + bl];

        float gi = 1.f / (1.f + expf(-pi));
        float gf = 1.f / (1.f + expf(-pf));
        float gg = tanhf(pg);
        float go = 1.f / (1.f + expf(-po));

        float cn = gf * c_st + gi * gg;
        float hn = go * tanhf(cn);

        bool msk = (t < len_b);
        if (msk) { c_st = cn; h_st = hn; }
        stcg_f(&g_H[p ^ 1][(b_pt << 9) + j_pt], h_st);

        __syncthreads();                 // all publishes in block issued
        if (tid == 0) bar_arrive(bq, e0 + t + 2);

        // DRAM out-stores + next-step xg prefetch hide under the spin
        size_t o = (size_t)b_pt * (SEQT * HC) + (size_t)t * HC + j_pt;
        out[o]                = msk ? hn : 0.f;
        out[OUT_CELL_OFF + o] = msk ? cn : 0.f;

        if (t + 1 < SEQT) {
            const float* xg = g_XG + (size_t)(t + 1) * (BATCH * G4)
                                   + (size_t)b_pt * G4;
            xi  = ldcg_f(xg + j_pt);
            xf  = ldcg_f(xg + 512 + j_pt);
            xgv = ldcg_f(xg + 1024 + j_pt);
            xo  = ldcg_f(xg + 1536 + j_pt);
        }

        bar_wait(bq, e0 + t + 2);   // per-warp acquire-poll (no extra sync)
    }

    // ---- final h, c ----
    {
        size_t e = (size_t)b_pt * HC + j_pt;
        out[OUT_H_OFF + e] = h_st;
        out[OUT_C_OFF + e] = c_st;
    }
#undef GEMV_BATCH
}

// ---------------------------------------------------------------------------
extern "C" void kernel_launch(void* const* d_in, const int* in_sizes, int n_in,
                              void* d_out, int out_size) {
    const int*   seq     = (const int*)d_in[0];
    const int*   lengths = (const int*)d_in[1];
    const float* emb     = (const float*)d_in[2];
    const float* W_ih    = (const float*)d_in[3];
    const float* W_hh    = (const float*)d_in[4];
    const float* b_ih    = (const float*)d_in[5];
    const float* b_hh    = (const float*)d_in[6];
    float* out = (float*)d_out;

    transpose_wih<<<dim3(64, 10), dim3(32, 8)>>>(W_ih);
    embed_gemm<<<dim3(G4 / BN, (SEQT * BATCH) / BM), 256>>>(seq, emb, b_ih, b_hh);
    lstm_persistent<<<NBLK, 256>>>(W_hh, lengths, out);
}

// round 8
// speedup vs baseline: 6.5933x; 1.2940x over previous
#include <cuda_runtime.h>
#include <math.h>
#include <stdint.h>

#define BATCH 64
#define SEQT  512
#define EDIM  300
#define KPAD  304
#define HC    512
#define G4    2048   // 4*HC
#define NBLK  128
#define NGRP  32     // blocks per bq barrier group

typedef unsigned long long ull;

// ---- scratch (device globals: allocation-free rule) ----
__device__ float g_XG[(size_t)SEQT * BATCH * G4];   // [t][b][g]
__device__ float g_WIT[KPAD * G4];                  // [k][g]
__device__ float g_H[2][BATCH * HC];                // double-buffered hidden (L2-scope)
__device__ unsigned int g_count4[4];                // per-bq barrier counters
__device__ unsigned int g_epoch4[4];                // per-bq barrier epochs

#define OUT_CELL_OFF  ((size_t)BATCH * SEQT * HC)
#define OUT_H_OFF     (2 * OUT_CELL_OFF)
#define OUT_C_OFF     (OUT_H_OFF + (size_t)BATCH * HC)

// ---------------- packed fp32x2 helpers (sm_100+) ----------------
__device__ __forceinline__ ull ffma2(ull a, ull b, ull c) {
    ull d;
    asm("fma.rn.f32x2 %0, %1, %2, %3;" : "=l"(d) : "l"(a), "l"(b), "l"(c));
    return d;
}
__device__ __forceinline__ ull pk2(float x, float y) {
    ull r;
    asm("mov.b64 %0, {%1, %2};" : "=l"(r)
        : "r"(__float_as_uint(x)), "r"(__float_as_uint(y)));
    return r;
}
__device__ __forceinline__ float hsum2(ull v) {
    unsigned a, b;
    asm("mov.b64 {%0, %1}, %2;" : "=r"(a), "=r"(b) : "l"(v));
    return __uint_as_float(a) + __uint_as_float(b);
}
__device__ __forceinline__ void unpk2(ull v, float& x, float& y) {
    unsigned a, b;
    asm("mov.b64 {%0, %1}, %2;" : "=r"(a), "=r"(b) : "l"(v));
    x = __uint_as_float(a); y = __uint_as_float(b);
}

// ---------------- fast, overflow-robust activations ----------------
__device__ __forceinline__ float fsigmoid(float x) {
    // __expf(-x) -> inf for very negative x => result 0 (correct limit)
    return __fdividef(1.f, 1.f + __expf(-x));
}
__device__ __forceinline__ float ftanh(float x) {
    float ax = fabsf(x);
    float e  = __expf(2.f * ax);                   // inf ok
    float r  = 1.f - __fdividef(2.f, e + 1.f);     // -> 1 at overflow
    return copysignf(r, x);
}

// ---------------- L2-scope (.cg) accessors ----------------
__device__ __forceinline__ float ldcg_f(const float* p) {
    float v;
    asm volatile("ld.global.cg.f32 %0, [%1];" : "=f"(v) : "l"(p));
    return v;
}
__device__ __forceinline__ void stcg_f(float* p, float v) {
    asm volatile("st.global.cg.f32 [%0], %1;" :: "l"(p), "f"(v));
}

// ---------------- cp.async (L2 -> SMEM, bypass L1) ----------------
__device__ __forceinline__ void cp16(unsigned smem_dst, const float* gsrc) {
    asm volatile("cp.async.cg.shared.global [%0], [%1], 16;"
                 :: "r"(smem_dst), "l"(gsrc));
}
#define CP_COMMIT()  asm volatile("cp.async.commit_group;" ::: "memory")
#define CP_WAIT(N)   asm volatile("cp.async.wait_group %0;" :: "n"(N) : "memory")

// ---------------- scoped-atomic barrier primitives ----------------
__device__ __forceinline__ unsigned ld_acq(const unsigned* p) {
    unsigned v;
    asm volatile("ld.acquire.gpu.global.u32 %0, [%1];" : "=r"(v) : "l"(p) : "memory");
    return v;
}
__device__ __forceinline__ void st_rel(unsigned* p, unsigned v) {
    asm volatile("st.release.gpu.global.u32 [%0], %1;" :: "l"(p), "r"(v) : "memory");
}
__device__ __forceinline__ unsigned atom_add_rel(unsigned* p, unsigned v) {
    unsigned old;
    asm volatile("atom.release.gpu.global.add.u32 %0, [%1], %2;"
                 : "=r"(old) : "l"(p), "r"(v) : "memory");
    return old;
}
__device__ __forceinline__ void bar_arrive(int bq, unsigned target) {
    if (atom_add_rel(&g_count4[bq], 1) == NGRP - 1) {
        g_count4[bq] = 0;
        st_rel(&g_epoch4[bq], target);
    }
}
__device__ __forceinline__ void bar_wait(int bq, unsigned target) {
    while (ld_acq(&g_epoch4[bq]) != target) { }
}

// ---------------------------------------------------------------------------
// Zero-prefill output + cell regions (poisoned by harness).
// ---------------------------------------------------------------------------
__global__ void zero_out(float* __restrict__ out) {
    size_t i = ((size_t)blockIdx.x * 256 + threadIdx.x) * 4;
    *(float4*)(out + i) = make_float4(0.f, 0.f, 0.f, 0.f);
}

// ---------------------------------------------------------------------------
// W_ih [2048,300] -> g_WIT [304,2048]
// ---------------------------------------------------------------------------
__global__ void transpose_wih(const float* __restrict__ W_ih) {
    __shared__ float tile[32][33];
    int n0 = blockIdx.x * 32;
    int k0 = blockIdx.y * 32;
    int tx = threadIdx.x;
    int ty = threadIdx.y;
#pragma unroll
    for (int i = 0; i < 32; i += 8) {
        int n = n0 + ty + i;
        int k = k0 + tx;
        tile[ty + i][tx] = (k < EDIM) ? W_ih[(size_t)n * EDIM + k] : 0.f;
    }
    __syncthreads();
#pragma unroll
    for (int i = 0; i < 32; i += 8) {
        int k = k0 + ty + i;
        int n = n0 + tx;
        if (k < KPAD) g_WIT[(size_t)k * G4 + n] = tile[tx][ty + i];
    }
}

// ---------------------------------------------------------------------------
// Input GEMM: XG[r][n] = emb[tok(r)] . WIT[:,n] + b_ih[n] + b_hh[n]
// Tile 128x128x16, 256 threads, 8x8 microtile (n split {tx*4, 64+tx*4}).
// ---------------------------------------------------------------------------
#define BM 128
#define BN 128
#define BK 16

__global__ void __launch_bounds__(256, 2) embed_gemm(
    const int* __restrict__ seq,
    const float* __restrict__ emb,
    const float* __restrict__ b_ih,
    const float* __restrict__ b_hh)
{
    __shared__ float As[BK][BM + 4];
    __shared__ float Bs[BK][BN];
    __shared__ int   toks[BM];

    int tid = threadIdx.x;
    int r0  = blockIdx.y * BM;
    int n0  = blockIdx.x * BN;

    if (tid < BM) {
        int r = r0 + tid;
        int b = r & 63;
        int t = r >> 6;
        toks[tid] = seq[b * SEQT + t];
    }
    __syncthreads();

    int tx = tid & 15;   // n
    int ty = tid >> 4;   // m octet

    ull acc[8][4];
#pragma unroll
    for (int i = 0; i < 8; i++)
#pragma unroll
        for (int j = 0; j < 4; j++) acc[i][j] = 0ull;

    for (int kb = 0; kb < KPAD; kb += BK) {
#pragma unroll
        for (int l = 0; l < 2; l++) {
            int fidx = tid + l * 256;
            int m    = fidx >> 2;
            int kq   = (fidx & 3) * 4;
            int k    = kb + kq;
            float4 v = make_float4(0.f, 0.f, 0.f, 0.f);
            if (k < EDIM)
                v = *(const float4*)(emb + (size_t)toks[m] * EDIM + k);
            As[kq + 0][m] = v.x;
            As[kq + 1][m] = v.y;
            As[kq + 2][m] = v.z;
            As[kq + 3][m] = v.w;
        }
#pragma unroll
        for (int l = 0; l < 2; l++) {
            int fidx = tid + l * 256;
            int k    = fidx >> 5;
            int nq   = (fidx & 31) * 4;
            float4 v = *(const float4*)(g_WIT + (size_t)(kb + k) * G4 + n0 + nq);
            *(float4*)&Bs[k][nq] = v;
        }
        __syncthreads();

#pragma unroll
        for (int k = 0; k < BK; k++) {
            ull b0 = *(const ull*)&Bs[k][tx * 4];
            ull b1 = *(const ull*)&Bs[k][tx * 4 + 2];
            ull b2 = *(const ull*)&Bs[k][64 + tx * 4];
            ull b3 = *(const ull*)&Bs[k][64 + tx * 4 + 2];
            float a[8];
            *(float4*)a       = *(const float4*)&As[k][ty * 8];
            *(float4*)(a + 4) = *(const float4*)&As[k][ty * 8 + 4];
#pragma unroll
            for (int i = 0; i < 8; i++) {
                ull aa = pk2(a[i], a[i]);
                acc[i][0] = ffma2(aa, b0, acc[i][0]);
                acc[i][1] = ffma2(aa, b1, acc[i][1]);
                acc[i][2] = ffma2(aa, b2, acc[i][2]);
                acc[i][3] = ffma2(aa, b3, acc[i][3]);
            }
        }
        __syncthreads();
    }

    int nA = n0 + tx * 4;
    int nB = n0 + 64 + tx * 4;
    float4 biA = *(const float4*)(b_ih + nA);
    float4 bhA = *(const float4*)(b_hh + nA);
    float4 biB = *(const float4*)(b_ih + nB);
    float4 bhB = *(const float4*)(b_hh + nB);

#pragma unroll
    for (int i = 0; i < 8; i++) {
        int r = r0 + ty * 8 + i;
        float x, y, z, w;
        unpk2(acc[i][0], x, y);
        unpk2(acc[i][1], z, w);
        float4 oA = make_float4(x + biA.x + bhA.x, y + biA.y + bhA.y,
                                z + biA.z + bhA.z, w + biA.w + bhA.w);
        unpk2(acc[i][2], x, y);
        unpk2(acc[i][3], z, w);
        float4 oB = make_float4(x + biB.x + bhB.x, y + biB.y + bhB.y,
                                z + biB.z + bhB.z, w + biB.w + bhB.w);
        *(float4*)(g_XG + (size_t)r * G4 + nA) = oA;
        *(float4*)(g_XG + (size_t)r * G4 + nB) = oB;
    }
}

// ---------------------------------------------------------------------------
// Persistent LSTM. 128 blocks = (jg 0..31) x (bq 0..3). Block owns 16 j-cols
// (64 W rows register-resident) x 16 batches. Per-batch GEMV skip once a
// sequence is finished; whole bq group exits at its max length (uniformly
// skipping the last barrier round so counters stay clean for graph replay).
// ---------------------------------------------------------------------------
__global__ void __launch_bounds__(256, 1) lstm_persistent(
    const float* __restrict__ W_hh,
    const int*   __restrict__ lengths,
    float* __restrict__ out)
{
    __shared__ float sm_h[16 * HC];    // 32 KB: this bq's h
    __shared__ float Ex[64 * 17];      // [lr][bl]
    __shared__ int   sl[16];           // group lengths

    const int tid  = threadIdx.x;
    const int bk   = blockIdx.x;
    const int jg   = bk >> 2;          // 0..31
    const int bq   = bk & 3;           // 0..3
    const int lane = tid & 31;
    const int w    = tid >> 5;         // 0..7
    const int rp   = lane >> 3;        // 0..3
    const int kc   = lane & 7;         // 0..7

    const int lr0 = w * 8 + rp * 2;
    const int lr1 = lr0 + 1;
    const int row0 = ((lr0 >> 4) << 9) + jg * 16 + (lr0 & 15);
    const int row1 = ((lr1 >> 4) << 9) + jg * 16 + (lr1 & 15);

    // --- W slice into registers
    ull W0[32], W1[32];
#pragma unroll
    for (int m = 0; m < 16; m++) {
        const float* p0 = W_hh + (size_t)row0 * HC + m * 32 + kc * 4;
        const float* p1 = W_hh + (size_t)row1 * HC + m * 32 + kc * 4;
        ulonglong2 v0 = *(const ulonglong2*)p0;
        ulonglong2 v1 = *(const ulonglong2*)p1;
        W0[2 * m] = v0.x; W0[2 * m + 1] = v0.y;
        W1[2 * m] = v1.x; W1[2 * m + 1] = v1.y;
    }

    const unsigned sm_h_u32 = (unsigned)__cvta_generic_to_shared(sm_h);

    // --- replay-safe epoch base
    const unsigned e0 = ld_acq(&g_epoch4[bq]);

    // --- group lengths + group max
    if (tid < 16) sl[tid] = lengths[bq * 16 + tid];

    // --- pointwise identity
    const int jl   = tid & 15;
    const int bl   = tid >> 4;          // 0..15
    const int b_pt = bq * 16 + bl;
    const int j_pt = jg * 16 + jl;
    float h_st = 0.f, c_st = 0.f;

    // --- init published h (parity 0)
    stcg_f(&g_H[0][(b_pt << 9) + j_pt], 0.f);

    __syncthreads();
    int gmax = sl[0];
#pragma unroll
    for (int i = 1; i < 16; i++) gmax = max(gmax, sl[i]);
    const int len_b = sl[bl];

    if (tid == 0) bar_arrive(bq, e0 + 1);
    bar_wait(bq, e0 + 1);

    // prefetch xg for t=0 (len >= 1 always)
    float xi, xf, xgv, xo;
    {
        const float* xg = g_XG + (size_t)b_pt * G4;
        xi  = ldcg_f(xg + j_pt);
        xf  = ldcg_f(xg + 512 + j_pt);
        xgv = ldcg_f(xg + 1024 + j_pt);
        xo  = ldcg_f(xg + 1536 + j_pt);
    }

#define GEMV_BATCH(bb)                                                        \
    if (t < sl[bb]) {                                                         \
        const float* hb = sm_h + ((bb) << 9) + (kc << 2);                     \
        ull a0 = 0ull, a1 = 0ull;                                             \
        _Pragma("unroll")                                                     \
        for (int m = 0; m < 16; m++) {                                        \
            ulonglong2 hv = *(const ulonglong2*)(hb + (m << 5));              \
            a0 = ffma2(W0[2 * m],     hv.x, a0);                              \
            a0 = ffma2(W0[2 * m + 1], hv.y, a0);                              \
            a1 = ffma2(W1[2 * m],     hv.x, a1);                              \
            a1 = ffma2(W1[2 * m + 1], hv.y, a1);                              \
        }                                                                     \
        float s0 = hsum2(a0);                                                 \
        float s1 = hsum2(a1);                                                 \
        s0 += __shfl_xor_sync(0xffffffffu, s0, 1);                            \
        s0 += __shfl_xor_sync(0xffffffffu, s0, 2);                            \
        s0 += __shfl_xor_sync(0xffffffffu, s0, 4);                            \
        s1 += __shfl_xor_sync(0xffffffffu, s1, 1);                            \
        s1 += __shfl_xor_sync(0xffffffffu, s1, 2);                            \
        s1 += __shfl_xor_sync(0xffffffffu, s1, 4);                            \
        if (kc == 0) {                                                        \
            Ex[lr0 * 17 + (bb)] = s0;                                         \
            Ex[lr1 * 17 + (bb)] = s1;                                         \
        }                                                                     \
    }

#pragma unroll 1
    for (int t = 0; t < gmax; t++) {
        const int p = t & 1;
        const float* h_in = g_H[p] + ((bq * 16) << 9);

        // ---- stage this bq's h (16 rows x 512) in two 8-batch halves ----
#pragma unroll
        for (int grp = 0; grp < 2; grp++) {
#pragma unroll
            for (int i = 0; i < 4; i++) {
                int lin = tid + (i << 8);
                int r   = lin >> 7;
                int off = (lin & 127) << 2;
                int b   = grp * 8 + r;
                cp16(sm_h_u32 + (unsigned)((((b << 9) + off) << 2)),
                     h_in + (b << 9) + off);
            }
            CP_COMMIT();
        }
        CP_WAIT(1);
        __syncthreads();

#pragma unroll 2
        for (int bb = 0; bb < 8; bb++) GEMV_BATCH(bb)

        CP_WAIT(0);
        __syncthreads();

#pragma unroll 2
        for (int bb = 8; bb < 16; bb++) GEMV_BATCH(bb)

        __syncthreads();       // Ex complete

        // ---- pointwise LSTM update (fast activations) ----
        const bool msk = (t < len_b);
        if (msk) {
            float pi = xi  + Ex[(0  + jl) * 17 + bl];
            float pf = xf  + Ex[(16 + jl) * 17 + bl];
            float pg = xgv + Ex[(32 + jl) * 17 + bl];
            float po = xo  + Ex[(48 + jl) * 17 + bl];

            float gi = fsigmoid(pi);
            float gf = fsigmoid(pf);
            float gg = ftanh(pg);
            float go = fsigmoid(po);

            c_st = gf * c_st + gi * gg;
            h_st = go * ftanh(c_st);
        }
        stcg_f(&g_H[p ^ 1][(b_pt << 9) + j_pt], h_st);

        const bool last = (t + 1 >= gmax);
        __syncthreads();                 // all publishes issued
        if (!last && tid == 0) bar_arrive(bq, e0 + t + 2);

        // active out-stores + next-step xg prefetch hide under the spin
        if (msk) {
            size_t o = (size_t)b_pt * (SEQT * HC) + (size_t)t * HC + j_pt;
            out[o]                = h_st;
            out[OUT_CELL_OFF + o] = c_st;
        }
        if (t + 1 < len_b) {
            const float* xg = g_XG + (size_t)(t + 1) * (BATCH * G4)
                                   + (size_t)b_pt * G4;
            xi  = ldcg_f(xg + j_pt);
            xf  = ldcg_f(xg + 512 + j_pt);
            xgv = ldcg_f(xg + 1024 + j_pt);
            xo  = ldcg_f(xg + 1536 + j_pt);
        }

        if (!last) bar_wait(bq, e0 + t + 2);
    }

    // ---- final h, c ----
    {
        size_t e = (size_t)b_pt * HC + j_pt;
        out[OUT_H_OFF + e] = h_st;
        out[OUT_C_OFF + e] = c_st;
    }
#undef GEMV_BATCH
}

// ---------------------------------------------------------------------------
extern "C" void kernel_launch(void* const* d_in, const int* in_sizes, int n_in,
                              void* d_out, int out_size) {
    const int*   seq     = (const int*)d_in[0];
    const int*   lengths = (const int*)d_in[1];
    const float* emb     = (const float*)d_in[2];
    const float* W_ih    = (const float*)d_in[3];
    const float* W_hh    = (const float*)d_in[4];
    const float* b_ih    = (const float*)d_in[5];
    const float* b_hh    = (const float*)d_in[6];
    float* out = (float*)d_out;

    // zero output/cell regions (2 * B*T*HC floats; float4 per thread)
    zero_out<<<(unsigned)(2 * OUT_CELL_OFF / (256 * 4)), 256>>>(out);
    transpose_wih<<<dim3(64, 10), dim3(32, 8)>>>(W_ih);
    embed_gemm<<<dim3(G4 / BN, (SEQT * BATCH) / BM), 256>>>(seq, emb, b_ih, b_hh);
    lstm_persistent<<<NBLK, 256>>>(W_hh, lengths, out);
}

// round 10
// speedup vs baseline: 7.2179x; 1.0947x over previous
#include <cuda_runtime.h>
#include <cuda_bf16.h>
#include <math.h>
#include <stdint.h>

#define BATCH 64
#define SEQT  512
#define EDIM  300
#define KB16  320      // bf16 K padding (one segment)
#define K3    960      // 3 segments: A=[hi,lo,hi], B=[hi,hi,lo]
#define HC    512
#define G4    2048     // 4*HC
#define NBLK  128
#define NGRP  32       // blocks per bq barrier group

typedef unsigned long long ull;

// ---- scratch (device globals: allocation-free rule) ----
__device__ float g_XG[(size_t)SEQT * BATCH * G4];          // [r][g]
__device__ unsigned short g_XB[(size_t)SEQT * BATCH * K3]; // bf16 A'' [r][960]
__device__ unsigned short g_WB[(size_t)G4 * K3];           // bf16 B'' [n][960]
__device__ float g_H[2][BATCH * HC];
__device__ unsigned int g_count4[4];
__device__ unsigned int g_epoch4[4];

#define OUT_CELL_OFF  ((size_t)BATCH * SEQT * HC)
#define OUT_H_OFF     (2 * OUT_CELL_OFF)
#define OUT_C_OFF     (OUT_H_OFF + (size_t)BATCH * HC)

// ---------------- packed fp32x2 helpers ----------------
__device__ __forceinline__ ull ffma2(ull a, ull b, ull c) {
    ull d;
    asm("fma.rn.f32x2 %0, %1, %2, %3;" : "=l"(d) : "l"(a), "l"(b), "l"(c));
    return d;
}
__device__ __forceinline__ float hsum2(ull v) {
    unsigned a, b;
    asm("mov.b64 {%0, %1}, %2;" : "=r"(a), "=r"(b) : "l"(v));
    return __uint_as_float(a) + __uint_as_float(b);
}

// ---------------- fast, overflow-robust activations ----------------
__device__ __forceinline__ float fsigmoid(float x) {
    return __fdividef(1.f, 1.f + __expf(-x));
}
__device__ __forceinline__ float ftanh(float x) {
    float ax = fabsf(x);
    float e  = __expf(2.f * ax);
    float r  = 1.f - __fdividef(2.f, e + 1.f);
    return copysignf(r, x);
}

// ---------------- L2-scope (.cg) accessors ----------------
__device__ __forceinline__ float ldcg_f(const float* p) {
    float v;
    asm volatile("ld.global.cg.f32 %0, [%1];" : "=f"(v) : "l"(p));
    return v;
}
__device__ __forceinline__ void stcg_f(float* p, float v) {
    asm volatile("st.global.cg.f32 [%0], %1;" :: "l"(p), "f"(v));
}

// ---------------- cp.async ----------------
__device__ __forceinline__ void cp16(unsigned smem_dst, const void* gsrc) {
    asm volatile("cp.async.cg.shared.global [%0], [%1], 16;"
                 :: "r"(smem_dst), "l"(gsrc));
}
#define CP_COMMIT()  asm volatile("cp.async.commit_group;" ::: "memory")
#define CP_WAIT(N)   asm volatile("cp.async.wait_group %0;" :: "n"(N) : "memory")

// ---------------- scoped-atomic barrier primitives ----------------
__device__ __forceinline__ unsigned ld_acq(const unsigned* p) {
    unsigned v;
    asm volatile("ld.acquire.gpu.global.u32 %0, [%1];" : "=r"(v) : "l"(p) : "memory");
    return v;
}
__device__ __forceinline__ void st_rel(unsigned* p, unsigned v) {
    asm volatile("st.release.gpu.global.u32 [%0], %1;" :: "l"(p), "r"(v) : "memory");
}
__device__ __forceinline__ unsigned atom_add_rel(unsigned* p, unsigned v) {
    unsigned old;
    asm volatile("atom.release.gpu.global.add.u32 %0, [%1], %2;"
                 : "=r"(old) : "l"(p), "r"(v) : "memory");
    return old;
}
__device__ __forceinline__ void bar_arrive(int bq, unsigned target) {
    if (atom_add_rel(&g_count4[bq], 1) == NGRP - 1) {
        g_count4[bq] = 0;
        st_rel(&g_epoch4[bq], target);
    }
}
__device__ __forceinline__ void bar_wait(int bq, unsigned target) {
    while (ld_acq(&g_epoch4[bq]) != target) { }
}

// ---------------- warp-level bf16 MMA (sm_80+ baseline PTX) ----------------
__device__ __forceinline__ void mma16816(float* d,
                                         const unsigned* a,
                                         const unsigned* b) {
    asm volatile(
        "mma.sync.aligned.m16n8k16.row.col.f32.bf16.bf16.f32 "
        "{%0,%1,%2,%3}, {%4,%5,%6,%7}, {%8,%9}, {%0,%1,%2,%3};"
        : "+f"(d[0]), "+f"(d[1]), "+f"(d[2]), "+f"(d[3])
        : "r"(a[0]), "r"(a[1]), "r"(a[2]), "r"(a[3]),
          "r"(b[0]), "r"(b[1]));
}

// ---------------------------------------------------------------------------
// Zero-prefill output + cell regions.
// ---------------------------------------------------------------------------
__global__ void zero_out(float* __restrict__ out) {
    size_t i = ((size_t)blockIdx.x * 256 + threadIdx.x) * 4;
    *(float4*)(out + i) = make_float4(0.f, 0.f, 0.f, 0.f);
}

// ---------------------------------------------------------------------------
// Build B'' = [hi(W), hi(W), lo(W)] bf16, K padded 300->320 with zeros.
// ---------------------------------------------------------------------------
__global__ void prep_WB(const float* __restrict__ W_ih) {
    int idx = blockIdx.x * 256 + threadIdx.x;   // 2048*320
    int n = idx / KB16;
    int k = idx - n * KB16;
    float w = (k < EDIM) ? W_ih[(size_t)n * EDIM + k] : 0.f;
    __nv_bfloat16 hi = __float2bfloat16(w);
    __nv_bfloat16 lo = __float2bfloat16(w - __bfloat162float(hi));
    unsigned short* p = g_WB + (size_t)n * K3;
    p[k]            = __bfloat16_as_ushort(hi);
    p[KB16 + k]     = __bfloat16_as_ushort(hi);
    p[2 * KB16 + k] = __bfloat16_as_ushort(lo);
}

// ---------------------------------------------------------------------------
// Build A'' = [hi(x), lo(x), hi(x)] bf16 per GEMM row r = t*64 + b.
// ---------------------------------------------------------------------------
__global__ void prep_X(const int* __restrict__ seq,
                       const float* __restrict__ emb) {
    size_t idx = (size_t)blockIdx.x * 256 + threadIdx.x;  // 32768*320
    int r = (int)(idx / KB16);
    int k = (int)(idx - (size_t)r * KB16);
    int b = r & 63;
    int t = r >> 6;
    int tok = seq[b * SEQT + t];
    float x = (k < EDIM) ? emb[(size_t)tok * EDIM + k] : 0.f;
    __nv_bfloat16 hi = __float2bfloat16(x);
    __nv_bfloat16 lo = __float2bfloat16(x - __bfloat162float(hi));
    unsigned short* p = g_XB + (size_t)r * K3;
    p[k]            = __bfloat16_as_ushort(hi);
    p[KB16 + k]     = __bfloat16_as_ushort(lo);
    p[2 * KB16 + k] = __bfloat16_as_ushort(hi);
}

// ---------------------------------------------------------------------------
// Tensor-core input GEMM via mma.sync m16n8k16 bf16.
// Block tile 128(M) x 128(N) x 32(K), 8 warps as 2(m) x 4(n), warp 64x32.
// Double-buffered cp.async smem tiles, pitch 40 halves (80B) => conflict-free
// quad-strided fragment LDS. Epilogue adds bias, stores float2.
// ---------------------------------------------------------------------------
#define KPITCH 40          // halves per row in smem (80 B)
#define NCHUNK 30          // 960 / 32

__global__ void __launch_bounds__(256) tc_embed_gemm(
    const float* __restrict__ b_ih,
    const float* __restrict__ b_hh)
{
    __shared__ __align__(16) unsigned short As[2][128 * KPITCH];
    __shared__ __align__(16) unsigned short Bs[2][128 * KPITCH];
    __shared__ float sbias[128];

    const int tid = threadIdx.x;
    const int wid = tid >> 5;
    const int lane = tid & 31;
    const int g   = lane >> 2;        // groupID 0..7
    const int t2  = lane & 3;         // threadID in group
    const int wm  = wid >> 2;         // 0..1
    const int wn  = wid & 3;          // 0..3

    const int mt = blockIdx.y;        // 0..255
    const int nt = blockIdx.x;        // 0..15

    if (tid < 128) {
        int n = nt * 128 + tid;
        sbias[tid] = b_ih[n] + b_hh[n];
    }

    const unsigned short* Abase = g_XB + (size_t)(mt * 128) * K3;
    const unsigned short* Bbase = g_WB + (size_t)(nt * 128) * K3;

    unsigned a_sm = 0, b_sm = 0;
    asm("{ .reg .u64 t; cvta.to.shared.u64 t, %1; cvt.u32.u64 %0, t; }"
        : "=r"(a_sm) : "l"((const void*)As));
    asm("{ .reg .u64 t; cvta.to.shared.u64 t, %1; cvt.u32.u64 %0, t; }"
        : "=r"(b_sm) : "l"((const void*)Bs));

#define LOAD_CHUNK(buf, c) do {                                               \
    _Pragma("unroll")                                                         \
    for (int i = 0; i < 2; i++) {                                             \
        int lin = tid + i * 256;         /* 0..511 */                         \
        int row = lin >> 2;                                                   \
        int q   = lin & 3;                                                    \
        cp16(a_sm + (buf) * (128 * KPITCH * 2) + row * (KPITCH * 2) + q * 16, \
             Abase + (size_t)row * K3 + (c) * 32 + q * 8);                    \
    }                                                                         \
    _Pragma("unroll")                                                         \
    for (int i = 0; i < 2; i++) {                                             \
        int lin = tid + i * 256;                                              \
        int row = lin >> 2;                                                   \
        int q   = lin & 3;                                                    \
        cp16(b_sm + (buf) * (128 * KPITCH * 2) + row * (KPITCH * 2) + q * 16, \
             Bbase + (size_t)row * K3 + (c) * 32 + q * 8);                    \
    }                                                                         \
    CP_COMMIT();                                                              \
} while (0)

    float acc[4][4][4];
#pragma unroll
    for (int mf = 0; mf < 4; mf++)
#pragma unroll
        for (int nf = 0; nf < 4; nf++)
#pragma unroll
            for (int q = 0; q < 4; q++) acc[mf][nf][q] = 0.f;

    LOAD_CHUNK(0, 0);

#pragma unroll 1
    for (int c = 0; c < NCHUNK; c++) {
        const int buf = c & 1;
        if (c + 1 < NCHUNK) {
            LOAD_CHUNK(buf ^ 1, c + 1);
            CP_WAIT(1);
        } else {
            CP_WAIT(0);
        }
        __syncthreads();

        const unsigned short* Ab = As[buf];
        const unsigned short* Bb = Bs[buf];

#pragma unroll
        for (int k16 = 0; k16 < 2; k16++) {
            const int ko = k16 * 16 + t2 * 2;
            unsigned af[4][4];
#pragma unroll
            for (int mf = 0; mf < 4; mf++) {
                int row = wm * 64 + mf * 16 + g;
                af[mf][0] = *(const unsigned*)&Ab[row * KPITCH + ko];
                af[mf][1] = *(const unsigned*)&Ab[(row + 8) * KPITCH + ko];
                af[mf][2] = *(const unsigned*)&Ab[row * KPITCH + ko + 8];
                af[mf][3] = *(const unsigned*)&Ab[(row + 8) * KPITCH + ko + 8];
            }
            unsigned bfr[4][2];
#pragma unroll
            for (int nf = 0; nf < 4; nf++) {
                int col = wn * 32 + nf * 8 + g;
                bfr[nf][0] = *(const unsigned*)&Bb[col * KPITCH + ko];
                bfr[nf][1] = *(const unsigned*)&Bb[col * KPITCH + ko + 8];
            }
#pragma unroll
            for (int mf = 0; mf < 4; mf++)
#pragma unroll
                for (int nf = 0; nf < 4; nf++)
                    mma16816(acc[mf][nf], af[mf], bfr[nf]);
        }
        __syncthreads();
    }
#undef LOAD_CHUNK

    // ---- epilogue: bias + store ----
    const int r0 = mt * 128 + wm * 64;
#pragma unroll
    for (int mf = 0; mf < 4; mf++) {
#pragma unroll
        for (int nf = 0; nf < 4; nf++) {
            int nl = wn * 32 + nf * 8 + t2 * 2;
            int n  = nt * 128 + nl;
            float bx = sbias[nl];
            float by = sbias[nl + 1];
            int ra = r0 + mf * 16 + g;
            int rb = ra + 8;
            *(float2*)(g_XG + (size_t)ra * G4 + n) =
                make_float2(acc[mf][nf][0] + bx, acc[mf][nf][1] + by);
            *(float2*)(g_XG + (size_t)rb * G4 + n) =
                make_float2(acc[mf][nf][2] + bx, acc[mf][nf][3] + by);
        }
    }
}

// ---------------------------------------------------------------------------
// Persistent LSTM (unchanged from R8).
// ---------------------------------------------------------------------------
__global__ void __launch_bounds__(256, 1) lstm_persistent(
    const float* __restrict__ W_hh,
    const int*   __restrict__ lengths,
    float* __restrict__ out)
{
    __shared__ float sm_h[16 * HC];
    __shared__ float Ex[64 * 17];
    __shared__ int   sl[16];

    const int tid  = threadIdx.x;
    const int bk   = blockIdx.x;
    const int jg   = bk >> 2;
    const int bq   = bk & 3;
    const int lane = tid & 31;
    const int w    = tid >> 5;
    const int rp   = lane >> 3;
    const int kc   = lane & 7;

    const int lr0 = w * 8 + rp * 2;
    const int lr1 = lr0 + 1;
    const int row0 = ((lr0 >> 4) << 9) + jg * 16 + (lr0 & 15);
    const int row1 = ((lr1 >> 4) << 9) + jg * 16 + (lr1 & 15);

    ull W0[32], W1[32];
#pragma unroll
    for (int m = 0; m < 16; m++) {
        const float* p0 = W_hh + (size_t)row0 * HC + m * 32 + kc * 4;
        const float* p1 = W_hh + (size_t)row1 * HC + m * 32 + kc * 4;
        ulonglong2 v0 = *(const ulonglong2*)p0;
        ulonglong2 v1 = *(const ulonglong2*)p1;
        W0[2 * m] = v0.x; W0[2 * m + 1] = v0.y;
        W1[2 * m] = v1.x; W1[2 * m + 1] = v1.y;
    }

    const unsigned sm_h_u32 = (unsigned)__cvta_generic_to_shared(sm_h);
    const unsigned e0 = ld_acq(&g_epoch4[bq]);

    if (tid < 16) sl[tid] = lengths[bq * 16 + tid];

    const int jl   = tid & 15;
    const int bl   = tid >> 4;
    const int b_pt = bq * 16 + bl;
    const int j_pt = jg * 16 + jl;
    float h_st = 0.f, c_st = 0.f;

    stcg_f(&g_H[0][(b_pt << 9) + j_pt], 0.f);

    __syncthreads();
    int gmax = sl[0];
#pragma unroll
    for (int i = 1; i < 16; i++) gmax = max(gmax, sl[i]);
    const int len_b = sl[bl];

    if (tid == 0) bar_arrive(bq, e0 + 1);
    bar_wait(bq, e0 + 1);

    float xi, xf, xgv, xo;
    {
        const float* xg = g_XG + (size_t)b_pt * G4;
        xi  = ldcg_f(xg + j_pt);
        xf  = ldcg_f(xg + 512 + j_pt);
        xgv = ldcg_f(xg + 1024 + j_pt);
        xo  = ldcg_f(xg + 1536 + j_pt);
    }

#define GEMV_BATCH(bb)                                                        \
    if (t < sl[bb]) {                                                         \
        const float* hb = sm_h + ((bb) << 9) + (kc << 2);                     \
        ull a0 = 0ull, a1 = 0ull;                                             \
        _Pragma("unroll")                                                     \
        for (int m = 0; m < 16; m++) {                                        \
            ulonglong2 hv = *(const ulonglong2*)(hb + (m << 5));              \
            a0 = ffma2(W0[2 * m],     hv.x, a0);                              \
            a0 = ffma2(W0[2 * m + 1], hv.y, a0);                              \
            a1 = ffma2(W1[2 * m],     hv.x, a1);                              \
            a1 = ffma2(W1[2 * m + 1], hv.y, a1);                              \
        }                                                                     \
        float s0 = hsum2(a0);                                                 \
        float s1 = hsum2(a1);                                                 \
        s0 += __shfl_xor_sync(0xffffffffu, s0, 1);                            \
        s0 += __shfl_xor_sync(0xffffffffu, s0, 2);                            \
        s0 += __shfl_xor_sync(0xffffffffu, s0, 4);                            \
        s1 += __shfl_xor_sync(0xffffffffu, s1, 1);                            \
        s1 += __shfl_xor_sync(0xffffffffu, s1, 2);                            \
        s1 += __shfl_xor_sync(0xffffffffu, s1, 4);                            \
        if (kc == 0) {                                                        \
            Ex[lr0 * 17 + (bb)] = s0;                                         \
            Ex[lr1 * 17 + (bb)] = s1;                                         \
        }                                                                     \
    }

#pragma unroll 1
    for (int t = 0; t < gmax; t++) {
        const int p = t & 1;
        const float* h_in = g_H[p] + ((bq * 16) << 9);

#pragma unroll
        for (int grp = 0; grp < 2; grp++) {
#pragma unroll
            for (int i = 0; i < 4; i++) {
                int lin = tid + (i << 8);
                int r   = lin >> 7;
                int off = (lin & 127) << 2;
                int b   = grp * 8 + r;
                cp16(sm_h_u32 + (unsigned)((((b << 9) + off) << 2)),
                     h_in + (b << 9) + off);
            }
            CP_COMMIT();
        }
        CP_WAIT(1);
        __syncthreads();

#pragma unroll 2
        for (int bb = 0; bb < 8; bb++) GEMV_BATCH(bb)

        CP_WAIT(0);
        __syncthreads();

#pragma unroll 2
        for (int bb = 8; bb < 16; bb++) GEMV_BATCH(bb)

        __syncthreads();

        const bool msk = (t < len_b);
        if (msk) {
            float pi = xi  + Ex[(0  + jl) * 17 + bl];
            float pf = xf  + Ex[(16 + jl) * 17 + bl];
            float pg = xgv + Ex[(32 + jl) * 17 + bl];
            float po = xo  + Ex[(48 + jl) * 17 + bl];

            float gi = fsigmoid(pi);
            float gf = fsigmoid(pf);
            float gg = ftanh(pg);
            float go = fsigmoid(po);

            c_st = gf * c_st + gi * gg;
            h_st = go * ftanh(c_st);
        }
        stcg_f(&g_H[p ^ 1][(b_pt << 9) + j_pt], h_st);

        const bool last = (t + 1 >= gmax);
        __syncthreads();
        if (!last && tid == 0) bar_arrive(bq, e0 + t + 2);

        if (msk) {
            size_t o = (size_t)b_pt * (SEQT * HC) + (size_t)t * HC + j_pt;
            out[o]                = h_st;
            out[OUT_CELL_OFF + o] = c_st;
        }
        if (t + 1 < len_b) {
            const float* xg = g_XG + (size_t)(t + 1) * (BATCH * G4)
                                   + (size_t)b_pt * G4;
            xi  = ldcg_f(xg + j_pt);
            xf  = ldcg_f(xg + 512 + j_pt);
            xgv = ldcg_f(xg + 1024 + j_pt);
            xo  = ldcg_f(xg + 1536 + j_pt);
        }

        if (!last) bar_wait(bq, e0 + t + 2);
    }

    {
        size_t e = (size_t)b_pt * HC + j_pt;
        out[OUT_H_OFF + e] = h_st;
        out[OUT_C_OFF + e] = c_st;
    }
#undef GEMV_BATCH
}

// ---------------------------------------------------------------------------
extern "C" void kernel_launch(void* const* d_in, const int* in_sizes, int n_in,
                              void* d_out, int out_size) {
    const int*   seq     = (const int*)d_in[0];
    const int*   lengths = (const int*)d_in[1];
    const float* emb     = (const float*)d_in[2];
    const float* W_ih    = (const float*)d_in[3];
    const float* W_hh    = (const float*)d_in[4];
    const float* b_ih    = (const float*)d_in[5];
    const float* b_hh    = (const float*)d_in[6];
    float* out = (float*)d_out;

    zero_out<<<(unsigned)(2 * OUT_CELL_OFF / (256 * 4)), 256>>>(out);
    prep_WB<<<(G4 * KB16) / 256, 256>>>(W_ih);
    prep_X<<<(unsigned)(((size_t)SEQT * BATCH * KB16) / 256), 256>>>(seq, emb);
    tc_embed_gemm<<<dim3(G4 / 128, (SEQT * BATCH) / 128), 256>>>(b_ih, b_hh);
    lstm_persistent<<<NBLK, 256>>>(W_hh, lengths, out);
}